// round 1
// baseline (speedup 1.0000x reference)
#include <cuda_runtime.h>
#include <math.h>

typedef unsigned long long ull;

// ---------------- problem constants ----------------
#define SEQ   256
#define BATCH 32
#define HID   1024
#define G4    4096            // 4*HID
#define KDIM  1024            // input dim == HID for all GEMMs here
#define MROWS (SEQ*BATCH)     // 8192

// output layout inside d_out (floats)
#define OUT_OUTPUT 0
#define OUT_HALL   (SEQ*BATCH*2*HID)              // 16777216
#define OUT_CALL   (OUT_HALL + 2*BATCH*2*HID)     // 16908288

// ---------------- device scratch (no mallocs allowed) ----------------
__device__ float g_xg  [2][SEQ*BATCH*G4];      // per-direction xg, reused per layer (268 MB)
__device__ float g_Wihp[2][2][G4*KDIM];        // [layer][dir] permuted W_ih (134 MB)
__device__ float g_Whhp[2][2][G4*KDIM];        // [layer][dir] permuted W_hh (134 MB)
__device__ float g_hbuf[2][SEQ*BATCH*HID];     // layer-0 outputs per dir (67 MB)
__device__ float g_hT  [2][2][HID*BATCH];      // [dir][pingpong] h transposed [k][b]
__device__ float g_cT  [2][HID*BATCH];         // [dir] c transposed [h][b]

// ---------------- packed f32x2 helpers ----------------
__device__ __forceinline__ ull pk2(float lo, float hi) {
    ull r; asm("mov.b64 %0, {%1, %2};" : "=l"(r) : "f"(lo), "f"(hi)); return r;
}
__device__ __forceinline__ void upk2(ull v, float& lo, float& hi) {
    asm("mov.b64 {%0, %1}, %2;" : "=f"(lo), "=f"(hi) : "l"(v));
}
__device__ __forceinline__ void fma2(ull& d, ull a, ull b) {
    asm("fma.rn.f32x2 %0, %1, %2, %0;" : "+l"(d) : "l"(a), "l"(b));
}

// ---------------- 1) weight repack: row g*H+h -> row 4h+g ----------------
// grid: (4096 rows, 8 matrices), 256 threads; each block copies one 1024-float row.
__global__ __launch_bounds__(256) void repack_kernel(
    const float* __restrict__ wihf, const float* __restrict__ whhf,
    const float* __restrict__ wihb, const float* __restrict__ whhb)
{
    int p = blockIdx.x;                    // output row 0..4095
    int m = blockIdx.y;                    // matrix id
    int dir   = m >> 2;
    int typ   = (m >> 1) & 1;              // 0 = ih, 1 = hh
    int layer = m & 1;
    int srow  = (p & 3) * HID + (p >> 2);  // source row g*H + h

    const float* base = dir ? (typ ? whhb : wihb) : (typ ? whhf : wihf);
    const float* src  = base + (size_t)layer * G4 * KDIM;
    float* dst = typ ? g_Whhp[layer][dir] : g_Wihp[layer][dir];

    int c = threadIdx.x * 4;
    float4 v = *(const float4*)&src[(size_t)srow * KDIM + c];
    *(float4*)&dst[(size_t)p * KDIM + c] = v;
}

// ---------------- 2) zero recurrent state ----------------
__global__ __launch_bounds__(512) void zero_state() {
    int i = blockIdx.x * blockDim.x + threadIdx.x;
    if (i < 2*2*HID*BATCH)              (&g_hT[0][0][0])[i] = 0.0f;
    else if (i < 2*2*HID*BATCH + 2*HID*BATCH)
                                         (&g_cT[0][0])[i - 2*2*HID*BATCH] = 0.0f;
}

// ---------------- 3) input GEMM: C[m][n] = sum_k A[m][k] * W[n][k] ----------------
// Tiles: BM=64, BN=64, BK=32. 256 threads, thread tile 4x4 (packed pairs along N).
// grid: (N/64=64, M/64=128, 2 dirs)
#define BM 64
#define BN 64
#define BK 32
__global__ __launch_bounds__(256) void gemm_xg(const float* __restrict__ x, int layer)
{
    int dir = blockIdx.z;
    const float* A = (layer == 0) ? x : g_hbuf[dir];
    const float* W = g_Wihp[layer][dir];
    float* C = g_xg[dir];

    __shared__ float As[BK][BM + 4];
    __shared__ float Bs[BK][BN + 4];

    int tid = threadIdx.x;
    int tx = tid & 15;          // N direction (16 * 4 = 64)
    int ty = tid >> 4;          // M direction (16 * 4 = 64)
    int m0 = blockIdx.y * BM;
    int n0 = blockIdx.x * BN;

    ull acc[4][2];
#pragma unroll
    for (int i = 0; i < 4; i++) { acc[i][0] = 0ull; acc[i][1] = 0ull; }

    int r  = tid >> 3;             // 0..31
    int kq = (tid & 7) << 2;       // 0,4,...,28

    for (int k0 = 0; k0 < KDIM; k0 += BK) {
#pragma unroll
        for (int it = 0; it < 2; it++) {
            float4 va = *(const float4*)&A[(size_t)(m0 + r + it*32) * KDIM + k0 + kq];
            As[kq+0][r+it*32] = va.x; As[kq+1][r+it*32] = va.y;
            As[kq+2][r+it*32] = va.z; As[kq+3][r+it*32] = va.w;
            float4 vb = *(const float4*)&W[(size_t)(n0 + r + it*32) * KDIM + k0 + kq];
            Bs[kq+0][r+it*32] = vb.x; Bs[kq+1][r+it*32] = vb.y;
            Bs[kq+2][r+it*32] = vb.z; Bs[kq+3][r+it*32] = vb.w;
        }
        __syncthreads();
#pragma unroll
        for (int k = 0; k < BK; k++) {
            float4 av = *(const float4*)&As[k][ty * 4];
            ulonglong2 bv = *(const ulonglong2*)&Bs[k][tx * 4];
            ull a;
            a = pk2(av.x, av.x); fma2(acc[0][0], a, bv.x); fma2(acc[0][1], a, bv.y);
            a = pk2(av.y, av.y); fma2(acc[1][0], a, bv.x); fma2(acc[1][1], a, bv.y);
            a = pk2(av.z, av.z); fma2(acc[2][0], a, bv.x); fma2(acc[2][1], a, bv.y);
            a = pk2(av.w, av.w); fma2(acc[3][0], a, bv.x); fma2(acc[3][1], a, bv.y);
        }
        __syncthreads();
    }
#pragma unroll
    for (int i = 0; i < 4; i++) {
        float4 o;
        upk2(acc[i][0], o.x, o.y);
        upk2(acc[i][1], o.z, o.w);
        *(float4*)&C[(size_t)(m0 + ty*4 + i) * G4 + n0 + tx*4] = o;
    }
}

// ---------------- 4) fused recurrent step ----------------
// gates[b][4h+g] = xg[time][b][4h+g] + sum_k h_prev[k][b] * Whh_p[4h+g][k]
// then LSTM pointwise update, write h to hT(out), layer output, and (time==S-1) h/c_last.
// grid: (64 column tiles, 2 dirs), 256 threads. Block tile: all 32 b x 64 j (=16 h).
__global__ __launch_bounds__(256) void lstm_step(int layer, int t, float* __restrict__ dout)
{
    int dir  = blockIdx.y;
    int time = dir ? (SEQ - 1 - t) : t;

    const float* W   = g_Whhp[layer][dir];
    const float* xg  = g_xg[dir] + (size_t)time * BATCH * G4;
    const float* hin = g_hT[dir][t & 1];
    float* hout = g_hT[dir][(t & 1) ^ 1];
    float* cT   = g_cT[dir];

    float* outp; int ostride;
    if (layer == 0) { outp = g_hbuf[dir] + (size_t)time * BATCH * HID; ostride = HID; }
    else            { outp = dout + (size_t)time * BATCH * (2*HID) + dir * HID; ostride = 2*HID; }
    float* hlast = dout + OUT_HALL + (size_t)layer * BATCH * (2*HID) + dir * HID;
    float* clast = dout + OUT_CALL + (size_t)layer * BATCH * (2*HID) + dir * HID;

    __shared__ float As[32][32];        // [k][b]  (hin is already [k][b])
    __shared__ float Bs[32][64 + 4];    // [k][j]

    int tid = threadIdx.x;
    int tx = tid & 15;          // j quad index: j = j0 + tx*4  (one full gate quad)
    int ty = tid >> 4;          // b pair: b = ty*2 + {0,1}
    int j0 = blockIdx.x * 64;

    ull acc00 = 0ull, acc01 = 0ull, acc10 = 0ull, acc11 = 0ull;

    int bL = tid & 31, kr = tid >> 5;   // A staging
    int r  = tid >> 3, kq = (tid & 7) << 2;  // B staging

    for (int k0 = 0; k0 < HID; k0 += 32) {
#pragma unroll
        for (int it = 0; it < 4; it++)
            As[kr + it*8][bL] = hin[(size_t)(k0 + kr + it*8) * BATCH + bL];
#pragma unroll
        for (int it = 0; it < 2; it++) {
            float4 vb = *(const float4*)&W[(size_t)(j0 + r + it*32) * KDIM + k0 + kq];
            Bs[kq+0][r+it*32] = vb.x; Bs[kq+1][r+it*32] = vb.y;
            Bs[kq+2][r+it*32] = vb.z; Bs[kq+3][r+it*32] = vb.w;
        }
        __syncthreads();
#pragma unroll
        for (int k = 0; k < 32; k++) {
            float2 av = *(const float2*)&As[k][ty * 2];
            ulonglong2 bv = *(const ulonglong2*)&Bs[k][tx * 4];
            ull a0 = pk2(av.x, av.x), a1 = pk2(av.y, av.y);
            fma2(acc00, a0, bv.x); fma2(acc01, a0, bv.y);
            fma2(acc10, a1, bv.x); fma2(acc11, a1, bv.y);
        }
        __syncthreads();
    }

    int h = (j0 >> 2) + tx;   // hidden index of this thread's gate quad
#pragma unroll
    for (int bi = 0; bi < 2; bi++) {
        int b = ty * 2 + bi;
        float gi, gf, gg, go;
        upk2(bi ? acc10 : acc00, gi, gf);
        upk2(bi ? acc11 : acc01, gg, go);
        float4 xv = *(const float4*)&xg[(size_t)b * G4 + j0 + tx*4];
        gi += xv.x; gf += xv.y; gg += xv.z; go += xv.w;

        float iv = 1.0f / (1.0f + expf(-gi));
        float fv = 1.0f / (1.0f + expf(-gf));
        float gv = tanhf(gg);
        float ov = 1.0f / (1.0f + expf(-go));

        int idx = h * BATCH + b;
        float c  = fv * cT[idx] + iv * gv;
        float hn = ov * tanhf(c);
        cT[idx]   = c;
        hout[idx] = hn;
        outp[(size_t)b * ostride + h] = hn;
        if (time == SEQ - 1) {             // fwd last step AND bwd first step
            hlast[(size_t)b * (2*HID) + h] = hn;
            clast[(size_t)b * (2*HID) + h] = c;
        }
    }
}

// ---------------- host launcher (graph-capturable: kernels only) ----------------
extern "C" void kernel_launch(void* const* d_in, const int* in_sizes, int n_in,
                              void* d_out, int out_size)
{
    const float* x    = (const float*)d_in[0];
    const float* wihf = (const float*)d_in[1];
    const float* whhf = (const float*)d_in[2];
    const float* wihb = (const float*)d_in[3];
    const float* whhb = (const float*)d_in[4];
    float* out = (float*)d_out;

    (void)in_sizes; (void)n_in; (void)out_size;

    repack_kernel<<<dim3(G4, 8), 256>>>(wihf, whhf, wihb, whhb);

    for (int layer = 0; layer < 2; layer++) {
        zero_state<<<384, 512>>>();
        gemm_xg<<<dim3(G4 / BN, MROWS / BM, 2), 256>>>(x, layer);
        for (int t = 0; t < SEQ; t++)
            lstm_step<<<dim3(G4 / 64, 2), 256>>>(layer, t, out);
    }
}

// round 2
// speedup vs baseline: 1.7980x; 1.7980x over previous
#include <cuda_runtime.h>
#include <math.h>
#include <stdint.h>

typedef unsigned long long ull;

// ---------------- problem constants ----------------
#define SEQ   256
#define BATCH 32
#define HID   1024
#define G4    4096
#define KDIM  1024
#define MROWS (SEQ*BATCH)

#define NCTA  256           // persistent grid size (2 dirs x 128 j-tiles)
#define KC    32            // k chunk per pipeline stage

// output layout inside d_out (floats)
#define OUT_HALL   (SEQ*BATCH*2*HID)
#define OUT_CALL   (OUT_HALL + 2*BATCH*2*HID)

// ---------------- device scratch ----------------
__device__ float g_xg  [2][SEQ*BATCH*G4];      // per-direction xg
__device__ float g_Wihp[2][2][G4*KDIM];        // [layer][dir] gate-permuted W_ih (row 4h+g)
__device__ float g_WhhT[2][2][KDIM*G4];        // [layer][dir] W_hh transposed: [k][4h+g]
__device__ float g_hbuf[2][SEQ*BATCH*HID];     // layer-0 outputs per dir
__device__ float g_hT  [2][2][HID*BATCH];      // [dir][pingpong] h transposed [k][b]
__device__ unsigned g_bar_count;
__device__ unsigned g_bar_gen;

// ---------------- packed f32x2 helpers ----------------
__device__ __forceinline__ ull pk2(float lo, float hi) {
    ull r; asm("mov.b64 %0, {%1, %2};" : "=l"(r) : "f"(lo), "f"(hi)); return r;
}
__device__ __forceinline__ void upk2(ull v, float& lo, float& hi) {
    asm("mov.b64 {%0, %1}, %2;" : "=f"(lo), "=f"(hi) : "l"(v));
}
__device__ __forceinline__ void fma2(ull& d, ull a, ull b) {
    asm("fma.rn.f32x2 %0, %1, %2, %0;" : "+l"(d) : "l"(a), "l"(b));
}

// ---------------- sync / async-copy helpers ----------------
__device__ __forceinline__ unsigned ld_acq(const unsigned* p) {
    unsigned v; asm volatile("ld.acquire.gpu.u32 %0, [%1];" : "=r"(v) : "l"(p) : "memory"); return v;
}
__device__ __forceinline__ void st_rel(unsigned* p, unsigned v) {
    asm volatile("st.release.gpu.u32 [%0], %1;" :: "l"(p), "r"(v) : "memory");
}
__device__ __forceinline__ unsigned atom_add_rel(unsigned* p, unsigned v) {
    unsigned o; asm volatile("atom.release.gpu.add.u32 %0, [%1], %2;"
                             : "=r"(o) : "l"(p), "r"(v) : "memory"); return o;
}
__device__ __forceinline__ void cp16(uint32_t s, const void* g) {
    asm volatile("cp.async.cg.shared.global [%0], [%1], 16;" :: "r"(s), "l"(g));
}
__device__ __forceinline__ void cp_commit() { asm volatile("cp.async.commit_group;"); }
__device__ __forceinline__ void cp_wait1()  { asm volatile("cp.async.wait_group 1;" ::: "memory"); }
__device__ __forceinline__ void cp_wait0()  { asm volatile("cp.async.wait_group 0;" ::: "memory"); }

// ---------------- 1a) W_ih gate-permute repack ----------------
// grid: (4096 rows, 4 matrices), 256 threads
__global__ __launch_bounds__(256) void repack_kernel(
    const float* __restrict__ wihf, const float* __restrict__ wihb)
{
    int p = blockIdx.x;
    int m = blockIdx.y;                    // 0..3
    int dir   = m >> 1;
    int layer = m & 1;
    int srow  = (p & 3) * HID + (p >> 2);

    const float* src = (dir ? wihb : wihf) + (size_t)layer * G4 * KDIM;
    float* dst = g_Wihp[layer][dir];

    int c = threadIdx.x * 4;
    float4 v = *(const float4*)&src[(size_t)srow * KDIM + c];
    *(float4*)&dst[(size_t)p * KDIM + c] = v;
}

// ---------------- 1b) W_hh transpose+permute: WhhT[k][4h+g] ----------------
// grid: (32 k-tiles, 128 p-tiles, 4 mats), block (32,8)
__global__ __launch_bounds__(256) void repackT_kernel(
    const float* __restrict__ whhf, const float* __restrict__ whhb)
{
    __shared__ float tile[32][33];
    int m = blockIdx.z;
    int dir = m >> 1, layer = m & 1;
    const float* src = (dir ? whhb : whhf) + (size_t)layer * G4 * KDIM;
    int k0 = blockIdx.x * 32, p0 = blockIdx.y * 32;
    int x = threadIdx.x, y = threadIdx.y;
#pragma unroll
    for (int i = 0; i < 4; i++) {
        int p = p0 + y + i * 8;
        int srow = (p & 3) * HID + (p >> 2);
        tile[y + i * 8][x] = src[(size_t)srow * KDIM + k0 + x];
    }
    __syncthreads();
    float* dst = g_WhhT[layer][dir];
#pragma unroll
    for (int i = 0; i < 4; i++) {
        int k = k0 + y + i * 8;
        dst[(size_t)k * G4 + p0 + x] = tile[x][y + i * 8];
    }
}

// ---------------- 2) zero recurrent state + barrier vars ----------------
__global__ __launch_bounds__(512) void zero_state() {
    int i = blockIdx.x * blockDim.x + threadIdx.x;
    if (i == 0) { g_bar_count = 0u; g_bar_gen = 0u; }
    if (i < 2 * 2 * HID * BATCH) (&g_hT[0][0][0])[i] = 0.0f;
}

// ---------------- 3) input GEMM: C[m][n] = sum_k A[m][k] * W[n][k] ----------------
// BM=128, BN=64, BK=32, 256 threads, thread tile 8m x 4n (f32x2 packed along n)
#define BM 128
#define BN 64
#define BK 32
__global__ __launch_bounds__(256) void gemm_xg(const float* __restrict__ x, int layer)
{
    int dir = blockIdx.z;
    const float* A = (layer == 0) ? x : g_hbuf[dir];
    const float* W = g_Wihp[layer][dir];
    float* C = g_xg[dir];

    __shared__ float As[BK][BM + 4];
    __shared__ float Bs[BK][BN + 4];

    int tid = threadIdx.x;
    int tx = tid & 15;          // n quad
    int ty = tid >> 4;          // m oct
    int m0 = blockIdx.y * BM;
    int n0 = blockIdx.x * BN;

    ull acc[8][2];
#pragma unroll
    for (int i = 0; i < 8; i++) { acc[i][0] = 0ull; acc[i][1] = 0ull; }

    int r  = tid >> 3;             // 0..31
    int kq = (tid & 7) << 2;       // 0,4,...,28

    for (int k0 = 0; k0 < KDIM; k0 += BK) {
#pragma unroll
        for (int it = 0; it < 4; it++) {
            float4 va = *(const float4*)&A[(size_t)(m0 + r + it*32) * KDIM + k0 + kq];
            As[kq+0][r+it*32] = va.x; As[kq+1][r+it*32] = va.y;
            As[kq+2][r+it*32] = va.z; As[kq+3][r+it*32] = va.w;
        }
#pragma unroll
        for (int it = 0; it < 2; it++) {
            float4 vb = *(const float4*)&W[(size_t)(n0 + r + it*32) * KDIM + k0 + kq];
            Bs[kq+0][r+it*32] = vb.x; Bs[kq+1][r+it*32] = vb.y;
            Bs[kq+2][r+it*32] = vb.z; Bs[kq+3][r+it*32] = vb.w;
        }
        __syncthreads();
#pragma unroll
        for (int k = 0; k < BK; k++) {
            float4 av0 = *(const float4*)&As[k][ty * 8];
            float4 av1 = *(const float4*)&As[k][ty * 8 + 4];
            ulonglong2 bv = *(const ulonglong2*)&Bs[k][tx * 4];
            ull a;
            a = pk2(av0.x, av0.x); fma2(acc[0][0], a, bv.x); fma2(acc[0][1], a, bv.y);
            a = pk2(av0.y, av0.y); fma2(acc[1][0], a, bv.x); fma2(acc[1][1], a, bv.y);
            a = pk2(av0.z, av0.z); fma2(acc[2][0], a, bv.x); fma2(acc[2][1], a, bv.y);
            a = pk2(av0.w, av0.w); fma2(acc[3][0], a, bv.x); fma2(acc[3][1], a, bv.y);
            a = pk2(av1.x, av1.x); fma2(acc[4][0], a, bv.x); fma2(acc[4][1], a, bv.y);
            a = pk2(av1.y, av1.y); fma2(acc[5][0], a, bv.x); fma2(acc[5][1], a, bv.y);
            a = pk2(av1.z, av1.z); fma2(acc[6][0], a, bv.x); fma2(acc[6][1], a, bv.y);
            a = pk2(av1.w, av1.w); fma2(acc[7][0], a, bv.x); fma2(acc[7][1], a, bv.y);
        }
        __syncthreads();
    }
#pragma unroll
    for (int i = 0; i < 8; i++) {
        float4 o;
        upk2(acc[i][0], o.x, o.y);
        upk2(acc[i][1], o.z, o.w);
        *(float4*)&C[(size_t)(m0 + ty*8 + i) * G4 + n0 + tx*4] = o;
    }
}

// ---------------- 4) persistent recurrent kernel ----------------
// One launch per layer runs all 256 steps. 256 CTAs = 2 dirs x 128 j-tiles (32 gate
// cols = 8 hidden each). Per step each CTA computes gates[32b x 32j] with a 4-way
// k-split across thread groups, reduces in smem, applies the LSTM pointwise update
// (cell state c lives in registers), writes h, then grid-syncs.
// smem: As[2][4][32][32] + Bs[2][4][32][32] + sRed[4][32][32] = 81920 B
#define SMEM_BYTES ((8192 + 8192 + 4096) * 4)

__global__ __launch_bounds__(256, 2) void lstm_persist(int layer, float* __restrict__ dout)
{
    extern __shared__ float sm[];
    float* As   = sm;            // 8192 floats
    float* Bs   = sm + 8192;     // 8192 floats
    float* sRed = sm + 16384;    // 4096 floats

    int tid = threadIdx.x;
    int cta = blockIdx.x;
    int dir = cta >> 7;
    int jt  = cta & 127;
    int j0  = jt * 32;

    const float* Wt = g_WhhT[layer][dir];       // [1024][4096]
    const float* xgbase = g_xg[dir];
    float* hb0 = g_hT[dir][0];
    float* hb1 = g_hT[dir][1];

    // GEMM roles
    int z  = tid >> 6;            // k slice 0..3
    int ty = (tid >> 3) & 7;      // b group (4 b)
    int tx = tid & 7;             // j quad
    // pointwise roles
    int hl = tid >> 5;            // 0..7
    int b  = tid & 31;
    int hg = jt * 8 + hl;         // global hidden index

    uint32_t sAs = (uint32_t)__cvta_generic_to_shared(As);
    uint32_t sBs = (uint32_t)__cvta_generic_to_shared(Bs);

    float c_reg = 0.0f;

    // per-thread staging decomposition (4 float4 each for As and Bs per chunk)
    int sf_z[4], sf_kl[4], sf_q[4];
#pragma unroll
    for (int i = 0; i < 4; i++) {
        int f = tid + i * 256;
        sf_z[i] = f >> 8; int rem = f & 255;
        sf_kl[i] = rem >> 3; sf_q[i] = rem & 7;
    }

    for (int t = 0; t < SEQ; t++) {
        int time = dir ? (SEQ - 1 - t) : t;
        const float* hin = (t & 1) ? hb1 : hb0;
        float* hout      = (t & 1) ? hb0 : hb1;

        // early xg prefetch (used in pointwise tail)
        float4 xv = *(const float4*)(xgbase + (size_t)time * BATCH * G4
                                     + (size_t)b * G4 + j0 + hl * 4);

        ull acc[4][2];
#pragma unroll
        for (int i = 0; i < 4; i++) { acc[i][0] = 0ull; acc[i][1] = 0ull; }

        auto stage = [&](int sbuf, int cb) {
#pragma unroll
            for (int i = 0; i < 4; i++) {
                int kg = (sf_z[i] << 8) + cb + sf_kl[i];
                int so = sbuf * 4096 + sf_z[i] * 1024 + sf_kl[i] * 32 + sf_q[i] * 4;
                cp16(sAs + (so << 2), hin + (size_t)kg * BATCH + sf_q[i] * 4);
                cp16(sBs + (so << 2), Wt + (size_t)kg * G4 + j0 + sf_q[i] * 4);
            }
            cp_commit();
        };

        stage(0, 0);
        int buf = 0;
#pragma unroll 1
        for (int ch = 0; ch < 8; ch++) {
            if (ch < 7) { stage(buf ^ 1, (ch + 1) * KC); cp_wait1(); }
            else        { cp_wait0(); }
            __syncthreads();                      // chunk ch fully staged
            const float* ap = As + buf * 4096 + z * 1024 + ty * 4;
            const float* bp = Bs + buf * 4096 + z * 1024 + tx * 4;
#pragma unroll
            for (int kl = 0; kl < KC; kl++) {
                float4 av = *(const float4*)(ap + kl * 32);
                ulonglong2 bv = *(const ulonglong2*)(bp + kl * 32);
                ull a;
                a = pk2(av.x, av.x); fma2(acc[0][0], a, bv.x); fma2(acc[0][1], a, bv.y);
                a = pk2(av.y, av.y); fma2(acc[1][0], a, bv.x); fma2(acc[1][1], a, bv.y);
                a = pk2(av.z, av.z); fma2(acc[2][0], a, bv.x); fma2(acc[2][1], a, bv.y);
                a = pk2(av.w, av.w); fma2(acc[3][0], a, bv.x); fma2(acc[3][1], a, bv.y);
            }
            __syncthreads();                      // done reading buf before restage
            buf ^= 1;
        }

        // partials -> sRed[z][b][j]
#pragma unroll
        for (int r = 0; r < 4; r++) {
            float4 o;
            upk2(acc[r][0], o.x, o.y);
            upk2(acc[r][1], o.z, o.w);
            *(float4*)&sRed[z * 1024 + (ty * 4 + r) * 32 + tx * 4] = o;
        }
        __syncthreads();

        // pointwise: thread owns (hg, b)
        float4 g0 = *(const float4*)&sRed[0 * 1024 + b * 32 + hl * 4];
        float4 g1 = *(const float4*)&sRed[1 * 1024 + b * 32 + hl * 4];
        float4 g2 = *(const float4*)&sRed[2 * 1024 + b * 32 + hl * 4];
        float4 g3 = *(const float4*)&sRed[3 * 1024 + b * 32 + hl * 4];
        float gi = g0.x + g1.x + g2.x + g3.x + xv.x;
        float gf = g0.y + g1.y + g2.y + g3.y + xv.y;
        float gg = g0.z + g1.z + g2.z + g3.z + xv.z;
        float go = g0.w + g1.w + g2.w + g3.w + xv.w;

        float iv = 1.0f / (1.0f + expf(-gi));
        float fv = 1.0f / (1.0f + expf(-gf));
        float gv = tanhf(gg);
        float ov = 1.0f / (1.0f + expf(-go));

        c_reg = fv * c_reg + iv * gv;
        float hn = ov * tanhf(c_reg);

        hout[hg * BATCH + b] = hn;
        if (layer == 0) {
            g_hbuf[dir][(size_t)time * BATCH * HID + (size_t)b * HID + hg] = hn;
        } else {
            dout[(size_t)time * BATCH * 2 * HID + (size_t)b * 2 * HID + dir * HID + hg] = hn;
        }
        if (time == SEQ - 1) {
            dout[OUT_HALL + (size_t)layer * BATCH * 2 * HID + (size_t)b * 2 * HID + dir * HID + hg] = hn;
            dout[OUT_CALL + (size_t)layer * BATCH * 2 * HID + (size_t)b * 2 * HID + dir * HID + hg] = c_reg;
        }

        // grid barrier (release h writes, acquire before next step's reads)
        if (t < SEQ - 1) {
            __syncthreads();
            if (tid == 0) {
                unsigned arr = atom_add_rel(&g_bar_count, 1u);
                if (arr == (unsigned)((t + 1) * NCTA - 1)) {
                    st_rel(&g_bar_gen, (unsigned)(t + 1));
                } else {
                    while (ld_acq(&g_bar_gen) < (unsigned)(t + 1)) { __nanosleep(64); }
                }
            }
            __syncthreads();
        }
    }
}

// ---------------- host launcher ----------------
extern "C" void kernel_launch(void* const* d_in, const int* in_sizes, int n_in,
                              void* d_out, int out_size)
{
    const float* x    = (const float*)d_in[0];
    const float* wihf = (const float*)d_in[1];
    const float* whhf = (const float*)d_in[2];
    const float* wihb = (const float*)d_in[3];
    const float* whhb = (const float*)d_in[4];
    float* out = (float*)d_out;
    (void)in_sizes; (void)n_in; (void)out_size;

    cudaFuncSetAttribute(lstm_persist, cudaFuncAttributeMaxDynamicSharedMemorySize, SMEM_BYTES);

    repack_kernel<<<dim3(G4, 4), 256>>>(wihf, wihb);
    repackT_kernel<<<dim3(32, 128, 4), dim3(32, 8)>>>(whhf, whhb);

    for (int layer = 0; layer < 2; layer++) {
        zero_state<<<256, 512>>>();
        gemm_xg<<<dim3(G4 / BN, MROWS / BM, 2), 256>>>(x, layer);
        lstm_persist<<<NCTA, 256, SMEM_BYTES>>>(layer, out);
    }
}

// round 4
// speedup vs baseline: 2.3049x; 1.2820x over previous
#include <cuda_runtime.h>
#include <cuda_bf16.h>
#include <math.h>
#include <stdint.h>

typedef unsigned long long ull;

// ---------------- problem constants ----------------
#define SEQ   256
#define BATCH 32
#define HID   1024
#define G4    4096
#define KDIM  1024
#define MROWS (SEQ*BATCH)

#define NCTA  256           // persistent grid size (2 dirs x 128 j-tiles)
#define KC    32            // k chunk per pipeline stage (recurrent kernel)

// output layout inside d_out (floats)
#define OUT_HALL   (SEQ*BATCH*2*HID)
#define OUT_CALL   (OUT_HALL + 2*BATCH*2*HID)

// ---------------- device scratch ----------------
__device__ float g_xg  [2][SEQ*BATCH*G4];        // per-direction xg
__device__ float g_WhhT[2][2][KDIM*G4];          // [layer][dir] W_hh transposed: [k][4h+g]
__device__ float g_hbuf[2][SEQ*BATCH*HID];       // layer-0 outputs per dir
__device__ float g_hT  [2][2][HID*BATCH];        // [dir][pingpong] h transposed [k][b]
__device__ __nv_bfloat16 g_Wph[2][2][G4*KDIM];   // gate-permuted W_ih hi
__device__ __nv_bfloat16 g_Wpl[2][2][G4*KDIM];   // gate-permuted W_ih lo
__device__ __nv_bfloat16 g_Ah[2][MROWS*KDIM];    // A hi ([0] for layer0, [dir] for layer1)
__device__ __nv_bfloat16 g_Al[2][MROWS*KDIM];    // A lo
__device__ unsigned g_bar_count;
__device__ unsigned g_bar_gen;

// ---------------- packed f32x2 helpers ----------------
__device__ __forceinline__ ull pk2(float lo, float hi) {
    ull r; asm("mov.b64 %0, {%1, %2};" : "=l"(r) : "f"(lo), "f"(hi)); return r;
}
__device__ __forceinline__ void upk2(ull v, float& lo, float& hi) {
    asm("mov.b64 {%0, %1}, %2;" : "=f"(lo), "=f"(hi) : "l"(v));
}
__device__ __forceinline__ void fma2(ull& d, ull a, ull b) {
    asm("fma.rn.f32x2 %0, %1, %2, %0;" : "+l"(d) : "l"(a), "l"(b));
}

// ---------------- sync / async-copy helpers ----------------
__device__ __forceinline__ unsigned ld_acq(const unsigned* p) {
    unsigned v; asm volatile("ld.acquire.gpu.u32 %0, [%1];" : "=r"(v) : "l"(p) : "memory"); return v;
}
__device__ __forceinline__ void st_rel(unsigned* p, unsigned v) {
    asm volatile("st.release.gpu.u32 [%0], %1;" :: "l"(p), "r"(v) : "memory");
}
__device__ __forceinline__ unsigned atom_add_rel(unsigned* p, unsigned v) {
    unsigned o; asm volatile("atom.release.gpu.add.u32 %0, [%1], %2;"
                             : "=r"(o) : "l"(p), "r"(v) : "memory"); return o;
}
__device__ __forceinline__ void cp16(uint32_t s, const void* g) {
    asm volatile("cp.async.cg.shared.global [%0], [%1], 16;" :: "r"(s), "l"(g));
}
__device__ __forceinline__ void cp_commit() { asm volatile("cp.async.commit_group;"); }
__device__ __forceinline__ void cp_wait1()  { asm volatile("cp.async.wait_group 1;" ::: "memory"); }
__device__ __forceinline__ void cp_wait0()  { asm volatile("cp.async.wait_group 0;" ::: "memory"); }

__device__ __forceinline__ uint32_t smem_u32(const void* p) {
    return (uint32_t)__cvta_generic_to_shared(p);
}

// ---------------- mma.sync / ldmatrix helpers (base PTX, sm_80+) ----------------
__device__ __forceinline__ void ldsm_x4(uint32_t& r0, uint32_t& r1, uint32_t& r2, uint32_t& r3,
                                        uint32_t addr) {
    asm volatile("ldmatrix.sync.aligned.m8n8.x4.shared.b16 {%0,%1,%2,%3}, [%4];"
                 : "=r"(r0), "=r"(r1), "=r"(r2), "=r"(r3) : "r"(addr));
}
__device__ __forceinline__ void mma_bf16(float& c0, float& c1, float& c2, float& c3,
                                         uint32_t a0, uint32_t a1, uint32_t a2, uint32_t a3,
                                         uint32_t b0, uint32_t b1) {
    asm volatile("mma.sync.aligned.m16n8k16.row.col.f32.bf16.bf16.f32 "
                 "{%0,%1,%2,%3}, {%4,%5,%6,%7}, {%8,%9}, {%0,%1,%2,%3};"
                 : "+f"(c0), "+f"(c1), "+f"(c2), "+f"(c3)
                 : "r"(a0), "r"(a1), "r"(a2), "r"(a3), "r"(b0), "r"(b1));
}

// ---------------- split-bf16 helper ----------------
__device__ __forceinline__ void split_bf16(float x, __nv_bfloat16& h, __nv_bfloat16& l) {
    h = __float2bfloat16_rn(x);
    l = __float2bfloat16_rn(x - __bfloat162float(h));
}

// ---------------- 1a) W_ih gate-permute + bf16 split: row g*H+h -> 4h+g ----------------
__global__ __launch_bounds__(256) void repack_wih_bf16(
    const float* __restrict__ wihf, const float* __restrict__ wihb)
{
    int p = blockIdx.x;
    int m = blockIdx.y;
    int dir   = m >> 1;
    int layer = m & 1;
    int srow  = (p & 3) * HID + (p >> 2);

    const float* src = (dir ? wihb : wihf) + (size_t)layer * G4 * KDIM;
    __nv_bfloat16* dh = g_Wph[layer][dir] + (size_t)p * KDIM;
    __nv_bfloat16* dl = g_Wpl[layer][dir] + (size_t)p * KDIM;

    int c = threadIdx.x * 4;
    float4 v = *(const float4*)&src[(size_t)srow * KDIM + c];
    __nv_bfloat16 h0, l0, h1, l1, h2, l2, h3, l3;
    split_bf16(v.x, h0, l0); split_bf16(v.y, h1, l1);
    split_bf16(v.z, h2, l2); split_bf16(v.w, h3, l3);
    __nv_bfloat162 hh0 = {h0, h1}, hh1 = {h2, h3};
    __nv_bfloat162 ll0 = {l0, l1}, ll1 = {l2, l3};
    *(__nv_bfloat162*)&dh[c]     = hh0; *(__nv_bfloat162*)&dh[c + 2] = hh1;
    *(__nv_bfloat162*)&dl[c]     = ll0; *(__nv_bfloat162*)&dl[c + 2] = ll1;
}

// ---------------- 1b) W_hh transpose+permute (fp32, recurrence) ----------------
__global__ __launch_bounds__(256) void repackT_kernel(
    const float* __restrict__ whhf, const float* __restrict__ whhb)
{
    __shared__ float tile[32][33];
    int m = blockIdx.z;
    int dir = m >> 1, layer = m & 1;
    const float* src = (dir ? whhb : whhf) + (size_t)layer * G4 * KDIM;
    int k0 = blockIdx.x * 32, p0 = blockIdx.y * 32;
    int x = threadIdx.x, y = threadIdx.y;
#pragma unroll
    for (int i = 0; i < 4; i++) {
        int p = p0 + y + i * 8;
        int srow = (p & 3) * HID + (p >> 2);
        tile[y + i * 8][x] = src[(size_t)srow * KDIM + k0 + x];
    }
    __syncthreads();
    float* dst = g_WhhT[layer][dir];
#pragma unroll
    for (int i = 0; i < 4; i++) {
        int k = k0 + y + i * 8;
        dst[(size_t)k * G4 + p0 + x] = tile[x][y + i * 8];
    }
}

// ---------------- 1c) fp32 -> bf16 hi/lo conversion for A ----------------
__global__ __launch_bounds__(256) void conv_A_bf16(const float* __restrict__ x, int mode)
{
    int dir = blockIdx.y;
    const float* src = mode ? g_hbuf[dir] : x;
    __nv_bfloat16* dh = g_Ah[mode ? dir : 0];
    __nv_bfloat16* dl = g_Al[mode ? dir : 0];
    size_t i = ((size_t)blockIdx.x * 256 + threadIdx.x) * 4;
    float4 v = *(const float4*)&src[i];
    __nv_bfloat16 h0, l0, h1, l1, h2, l2, h3, l3;
    split_bf16(v.x, h0, l0); split_bf16(v.y, h1, l1);
    split_bf16(v.z, h2, l2); split_bf16(v.w, h3, l3);
    __nv_bfloat162 hh0 = {h0, h1}, hh1 = {h2, h3};
    __nv_bfloat162 ll0 = {l0, l1}, ll1 = {l2, l3};
    *(__nv_bfloat162*)&dh[i]     = hh0; *(__nv_bfloat162*)&dh[i + 2] = hh1;
    *(__nv_bfloat162*)&dl[i]     = ll0; *(__nv_bfloat162*)&dl[i + 2] = ll1;
}

// ---------------- 2) zero recurrent state + barrier vars ----------------
__global__ __launch_bounds__(512) void zero_state() {
    int i = blockIdx.x * blockDim.x + threadIdx.x;
    if (i == 0) { g_bar_count = 0u; g_bar_gen = 0u; }
    if (i < 2 * 2 * HID * BATCH) (&g_hT[0][0][0])[i] = 0.0f;
}

// ---------------- 3) input GEMM via mma.sync bf16 split ----------------
// C[m][n] = sum_k A[m][k]*W[n][k] as Ah*Wh + Ah*Wl + Al*Wh (fp32 accum).
// BM=128, BN=64, BK=32. 8 warps (4m x 2n), warp tile 32x32.
// SMEM stage (bf16 elems, padded stride 40): Ah[128*40] Al Wh[64*40] Wl = 15360 elems.
#define GM_SA  40
#define GM_AH  0
#define GM_AL  5120
#define GM_WH  10240
#define GM_WL  12800
#define GM_STG 15360
#define GM_SMEM (2 * GM_STG * 2)   // bytes

__global__ __launch_bounds__(256, 2) void gemm_mma(int layer)
{
    extern __shared__ __nv_bfloat16 gsm[];

    int tid = threadIdx.x;
    int wid = tid >> 5;
    int lane = tid & 31;
    int dir = blockIdx.z;
    int n0 = blockIdx.x * 64;
    int m0 = blockIdx.y * 128;

    const __nv_bfloat16* Ah = g_Ah[layer == 0 ? 0 : dir];
    const __nv_bfloat16* Al = g_Al[layer == 0 ? 0 : dir];
    const __nv_bfloat16* Wh = g_Wph[layer][dir];
    const __nv_bfloat16* Wl = g_Wpl[layer][dir];

    uint32_t sb = smem_u32(gsm);

    // ---- staging (cp.async): per chunk 6 cp16 per thread ----
    int arow0 = tid >> 2, aq = tid & 3;              // A: 2 iters of (row,q)
    int wrow  = tid >> 2, wq = tid & 3;              // W: 1 iter (rows 0..63)
    auto stage = [&](int buf, int k0) {
        uint32_t base = sb + buf * GM_STG * 2;
#pragma unroll
        for (int i = 0; i < 2; i++) {
            int row = arow0 + i * 64;
            uint32_t d = base + (row * GM_SA + aq * 8) * 2;
            size_t s = (size_t)(m0 + row) * KDIM + k0 + aq * 8;
            cp16(d + GM_AH * 2, Ah + s);
            cp16(d + GM_AL * 2, Al + s);
        }
        {
            uint32_t d = base + (wrow * GM_SA + wq * 8) * 2;
            size_t s = (size_t)(n0 + wrow) * KDIM + k0 + wq * 8;
            cp16(d + GM_WH * 2, Wh + s);
            cp16(d + GM_WL * 2, Wl + s);
        }
        cp_commit();
    };

    // ---- ldmatrix base offsets (elements) ----
    int m0w = (wid >> 1) * 32;
    int n0w = (wid & 1) * 32;
    // A tile addr: row = m0w + mi*16 + (lane&15), col = ks*16 + (lane>>4)*8
    int a_row = m0w + (lane & 15);
    int a_col = (lane >> 4) * 8;
    // W tile addr: tile = lane>>3, r = lane&7:
    //   n = n0w + jp*16 + (tile>>1)*8 + r, col = ks*16 + (tile&1)*8
    int w_n   = n0w + ((lane >> 4) & 1) * 8 + (lane & 7);
    int w_col = ((lane >> 3) & 1) * 8;

    float acc[2][4][4];
#pragma unroll
    for (int mi = 0; mi < 2; mi++)
#pragma unroll
        for (int j = 0; j < 4; j++)
#pragma unroll
            for (int e = 0; e < 4; e++) acc[mi][j][e] = 0.0f;

    stage(0, 0);
    int buf = 0;
#pragma unroll 1
    for (int ch = 0; ch < KDIM / 32; ch++) {
        if (ch < KDIM / 32 - 1) { stage(buf ^ 1, (ch + 1) * 32); cp_wait1(); }
        else                    { cp_wait0(); }
        __syncthreads();
        uint32_t base = sb + buf * GM_STG * 2;
#pragma unroll
        for (int ks = 0; ks < 2; ks++) {
            uint32_t aH[2][4], aL[2][4], wH[2][4], wL[2][4];
#pragma unroll
            for (int mi = 0; mi < 2; mi++) {
                uint32_t ao = base + ((a_row + mi * 16) * GM_SA + ks * 16 + a_col) * 2;
                ldsm_x4(aH[mi][0], aH[mi][1], aH[mi][2], aH[mi][3], ao + GM_AH * 2);
                ldsm_x4(aL[mi][0], aL[mi][1], aL[mi][2], aL[mi][3], ao + GM_AL * 2);
            }
#pragma unroll
            for (int jp = 0; jp < 2; jp++) {
                uint32_t wo = base + ((w_n + jp * 16) * GM_SA + ks * 16 + w_col) * 2;
                ldsm_x4(wH[jp][0], wH[jp][1], wH[jp][2], wH[jp][3], wo + GM_WH * 2);
                ldsm_x4(wL[jp][0], wL[jp][1], wL[jp][2], wL[jp][3], wo + GM_WL * 2);
            }
#pragma unroll
            for (int mi = 0; mi < 2; mi++) {
#pragma unroll
                for (int j = 0; j < 4; j++) {
                    int jp = j >> 1, hi = (j & 1) * 2;
                    float* c = acc[mi][j];
                    mma_bf16(c[0], c[1], c[2], c[3],
                             aH[mi][0], aH[mi][1], aH[mi][2], aH[mi][3],
                             wH[jp][hi], wH[jp][hi + 1]);
                    mma_bf16(c[0], c[1], c[2], c[3],
                             aH[mi][0], aH[mi][1], aH[mi][2], aH[mi][3],
                             wL[jp][hi], wL[jp][hi + 1]);
                    mma_bf16(c[0], c[1], c[2], c[3],
                             aL[mi][0], aL[mi][1], aL[mi][2], aL[mi][3],
                             wH[jp][hi], wH[jp][hi + 1]);
                }
            }
        }
        __syncthreads();
        buf ^= 1;
    }

    // ---- epilogue: write fp32 gates ----
    float* C = g_xg[dir];
    int g = lane >> 2, q = lane & 3;
#pragma unroll
    for (int mi = 0; mi < 2; mi++) {
        int row = m0 + m0w + mi * 16 + g;
#pragma unroll
        for (int j = 0; j < 4; j++) {
            int col = n0 + n0w + j * 8 + q * 2;
            float2 v0 = { acc[mi][j][0], acc[mi][j][1] };
            float2 v1 = { acc[mi][j][2], acc[mi][j][3] };
            *(float2*)&C[(size_t)row * G4 + col]       = v0;
            *(float2*)&C[(size_t)(row + 8) * G4 + col] = v1;
        }
    }
}

// ---------------- 4) persistent recurrent kernel (unchanged from R2) ----------------
#define SMEM_BYTES ((8192 + 8192 + 4096) * 4)

__global__ __launch_bounds__(256, 2) void lstm_persist(int layer, float* __restrict__ dout)
{
    extern __shared__ float sm[];
    float* As   = sm;
    float* Bs   = sm + 8192;
    float* sRed = sm + 16384;

    int tid = threadIdx.x;
    int cta = blockIdx.x;
    int dir = cta >> 7;
    int jt  = cta & 127;
    int j0  = jt * 32;

    const float* Wt = g_WhhT[layer][dir];
    const float* xgbase = g_xg[dir];
    float* hb0 = g_hT[dir][0];
    float* hb1 = g_hT[dir][1];

    int z  = tid >> 6;
    int ty = (tid >> 3) & 7;
    int tx = tid & 7;
    int hl = tid >> 5;
    int b  = tid & 31;
    int hg = jt * 8 + hl;

    uint32_t sAs = smem_u32(As);
    uint32_t sBs = smem_u32(Bs);

    float c_reg = 0.0f;

    int sf_z[4], sf_kl[4], sf_q[4];
#pragma unroll
    for (int i = 0; i < 4; i++) {
        int f = tid + i * 256;
        sf_z[i] = f >> 8; int rem = f & 255;
        sf_kl[i] = rem >> 3; sf_q[i] = rem & 7;
    }

    for (int t = 0; t < SEQ; t++) {
        int time = dir ? (SEQ - 1 - t) : t;
        const float* hin = (t & 1) ? hb1 : hb0;
        float* hout      = (t & 1) ? hb0 : hb1;

        float4 xv = *(const float4*)(xgbase + (size_t)time * BATCH * G4
                                     + (size_t)b * G4 + j0 + hl * 4);

        ull acc[4][2];
#pragma unroll
        for (int i = 0; i < 4; i++) { acc[i][0] = 0ull; acc[i][1] = 0ull; }

        auto stage = [&](int sbuf, int cb) {
#pragma unroll
            for (int i = 0; i < 4; i++) {
                int kg = (sf_z[i] << 8) + cb + sf_kl[i];
                int so = sbuf * 4096 + sf_z[i] * 1024 + sf_kl[i] * 32 + sf_q[i] * 4;
                cp16(sAs + (so << 2), hin + (size_t)kg * BATCH + sf_q[i] * 4);
                cp16(sBs + (so << 2), Wt + (size_t)kg * G4 + j0 + sf_q[i] * 4);
            }
            cp_commit();
        };

        stage(0, 0);
        int buf = 0;
#pragma unroll 1
        for (int ch = 0; ch < 8; ch++) {
            if (ch < 7) { stage(buf ^ 1, (ch + 1) * KC); cp_wait1(); }
            else        { cp_wait0(); }
            __syncthreads();
            const float* ap = As + buf * 4096 + z * 1024 + ty * 4;
            const float* bp = Bs + buf * 4096 + z * 1024 + tx * 4;
#pragma unroll
            for (int kl = 0; kl < KC; kl++) {
                float4 av = *(const float4*)(ap + kl * 32);
                ulonglong2 bv = *(const ulonglong2*)(bp + kl * 32);
                ull a;
                a = pk2(av.x, av.x); fma2(acc[0][0], a, bv.x); fma2(acc[0][1], a, bv.y);
                a = pk2(av.y, av.y); fma2(acc[1][0], a, bv.x); fma2(acc[1][1], a, bv.y);
                a = pk2(av.z, av.z); fma2(acc[2][0], a, bv.x); fma2(acc[2][1], a, bv.y);
                a = pk2(av.w, av.w); fma2(acc[3][0], a, bv.x); fma2(acc[3][1], a, bv.y);
            }
            __syncthreads();
            buf ^= 1;
        }

#pragma unroll
        for (int r = 0; r < 4; r++) {
            float4 o;
            upk2(acc[r][0], o.x, o.y);
            upk2(acc[r][1], o.z, o.w);
            *(float4*)&sRed[z * 1024 + (ty * 4 + r) * 32 + tx * 4] = o;
        }
        __syncthreads();

        float4 g0 = *(const float4*)&sRed[0 * 1024 + b * 32 + hl * 4];
        float4 g1 = *(const float4*)&sRed[1 * 1024 + b * 32 + hl * 4];
        float4 g2 = *(const float4*)&sRed[2 * 1024 + b * 32 + hl * 4];
        float4 g3 = *(const float4*)&sRed[3 * 1024 + b * 32 + hl * 4];
        float gi = g0.x + g1.x + g2.x + g3.x + xv.x;
        float gf = g0.y + g1.y + g2.y + g3.y + xv.y;
        float gg = g0.z + g1.z + g2.z + g3.z + xv.z;
        float go = g0.w + g1.w + g2.w + g3.w + xv.w;

        float iv = 1.0f / (1.0f + expf(-gi));
        float fv = 1.0f / (1.0f + expf(-gf));
        float gv = tanhf(gg);
        float ov = 1.0f / (1.0f + expf(-go));

        c_reg = fv * c_reg + iv * gv;
        float hn = ov * tanhf(c_reg);

        hout[hg * BATCH + b] = hn;
        if (layer == 0) {
            g_hbuf[dir][(size_t)time * BATCH * HID + (size_t)b * HID + hg] = hn;
        } else {
            dout[(size_t)time * BATCH * 2 * HID + (size_t)b * 2 * HID + dir * HID + hg] = hn;
        }
        if (time == SEQ - 1) {
            dout[OUT_HALL + (size_t)layer * BATCH * 2 * HID + (size_t)b * 2 * HID + dir * HID + hg] = hn;
            dout[OUT_CALL + (size_t)layer * BATCH * 2 * HID + (size_t)b * 2 * HID + dir * HID + hg] = c_reg;
        }

        if (t < SEQ - 1) {
            __syncthreads();
            if (tid == 0) {
                unsigned arr = atom_add_rel(&g_bar_count, 1u);
                if (arr == (unsigned)((t + 1) * NCTA - 1)) {
                    st_rel(&g_bar_gen, (unsigned)(t + 1));
                } else {
                    while (ld_acq(&g_bar_gen) < (unsigned)(t + 1)) { __nanosleep(64); }
                }
            }
            __syncthreads();
        }
    }
}

// ---------------- host launcher ----------------
extern "C" void kernel_launch(void* const* d_in, const int* in_sizes, int n_in,
                              void* d_out, int out_size)
{
    const float* x    = (const float*)d_in[0];
    const float* wihf = (const float*)d_in[1];
    const float* whhf = (const float*)d_in[2];
    const float* wihb = (const float*)d_in[3];
    const float* whhb = (const float*)d_in[4];
    float* out = (float*)d_out;
    (void)in_sizes; (void)n_in; (void)out_size;

    cudaFuncSetAttribute(lstm_persist, cudaFuncAttributeMaxDynamicSharedMemorySize, SMEM_BYTES);
    cudaFuncSetAttribute(gemm_mma,     cudaFuncAttributeMaxDynamicSharedMemorySize, GM_SMEM);

    repack_wih_bf16<<<dim3(G4, 4), 256>>>(wihf, wihb);
    repackT_kernel<<<dim3(32, 128, 4), dim3(32, 8)>>>(whhf, whhb);
    conv_A_bf16<<<dim3(MROWS * KDIM / 1024, 1), 256>>>(x, 0);

    for (int layer = 0; layer < 2; layer++) {
        zero_state<<<256, 512>>>();
        gemm_mma<<<dim3(G4 / 64, MROWS / 128, 2), 256, GM_SMEM>>>(layer);
        lstm_persist<<<NCTA, 256, SMEM_BYTES>>>(layer, out);
        if (layer == 0)
            conv_A_bf16<<<dim3(MROWS * KDIM / 1024, 2), 256>>>(x, 1);
    }
}

// round 5
// speedup vs baseline: 2.8130x; 1.2204x over previous
#include <cuda_runtime.h>
#include <cuda_bf16.h>
#include <math.h>
#include <stdint.h>

typedef unsigned long long ull;

// ---------------- problem constants ----------------
#define SEQ   256
#define BATCH 32
#define HID   1024
#define G4    4096
#define KDIM  1024
#define MROWS (SEQ*BATCH)

#define NCTA  128           // persistent grid (2 dirs x 64 j-tiles of 64 gate cols)

// output layout inside d_out (floats)
#define OUT_HALL   (SEQ*BATCH*2*HID)
#define OUT_CALL   (OUT_HALL + 2*BATCH*2*HID)

// ---------------- device scratch ----------------
__device__ float g_xg  [2][SEQ*BATCH*G4];          // per-direction xg
__device__ __nv_bfloat16 g_Wph[2][2][G4*KDIM];     // gate-permuted W_ih hi
__device__ __nv_bfloat16 g_Wpl[2][2][G4*KDIM];     // gate-permuted W_ih lo
__device__ __nv_bfloat16 g_Whh_h[2][2][G4*KDIM];   // gate-permuted W_hh hi
__device__ __nv_bfloat16 g_Whh_l[2][2][G4*KDIM];   // gate-permuted W_hh lo
__device__ __nv_bfloat16 g_Ah[2][MROWS*KDIM];      // GEMM A hi ([0]=x for layer0, [dir] for layer1)
__device__ __nv_bfloat16 g_Al[2][MROWS*KDIM];      // GEMM A lo
__device__ __nv_bfloat16 g_hb16[2*2*2*BATCH*HID];  // [dir][pp][hi/lo][b][k] recurrent h
__device__ unsigned g_bar_count;
__device__ unsigned g_bar_gen;

// ---------------- sync / async-copy helpers ----------------
__device__ __forceinline__ unsigned ld_acq(const unsigned* p) {
    unsigned v; asm volatile("ld.acquire.gpu.u32 %0, [%1];" : "=r"(v) : "l"(p) : "memory"); return v;
}
__device__ __forceinline__ void st_rel(unsigned* p, unsigned v) {
    asm volatile("st.release.gpu.u32 [%0], %1;" :: "l"(p), "r"(v) : "memory");
}
__device__ __forceinline__ unsigned atom_add_rel(unsigned* p, unsigned v) {
    unsigned o; asm volatile("atom.release.gpu.add.u32 %0, [%1], %2;"
                             : "=r"(o) : "l"(p), "r"(v) : "memory"); return o;
}
__device__ __forceinline__ void cp16(uint32_t s, const void* g) {
    asm volatile("cp.async.cg.shared.global [%0], [%1], 16;" :: "r"(s), "l"(g));
}
__device__ __forceinline__ void cp_commit() { asm volatile("cp.async.commit_group;"); }
__device__ __forceinline__ void cp_wait1()  { asm volatile("cp.async.wait_group 1;" ::: "memory"); }
__device__ __forceinline__ void cp_wait0()  { asm volatile("cp.async.wait_group 0;" ::: "memory"); }

__device__ __forceinline__ uint32_t smem_u32(const void* p) {
    return (uint32_t)__cvta_generic_to_shared(p);
}

// ---------------- mma.sync / ldmatrix helpers (base PTX, sm_80+) ----------------
__device__ __forceinline__ void ldsm_x4(uint32_t& r0, uint32_t& r1, uint32_t& r2, uint32_t& r3,
                                        uint32_t addr) {
    asm volatile("ldmatrix.sync.aligned.m8n8.x4.shared.b16 {%0,%1,%2,%3}, [%4];"
                 : "=r"(r0), "=r"(r1), "=r"(r2), "=r"(r3) : "r"(addr));
}
__device__ __forceinline__ void ldsm_x2(uint32_t& r0, uint32_t& r1, uint32_t addr) {
    asm volatile("ldmatrix.sync.aligned.m8n8.x2.shared.b16 {%0,%1}, [%2];"
                 : "=r"(r0), "=r"(r1) : "r"(addr));
}
__device__ __forceinline__ void mma_bf16(float& c0, float& c1, float& c2, float& c3,
                                         uint32_t a0, uint32_t a1, uint32_t a2, uint32_t a3,
                                         uint32_t b0, uint32_t b1) {
    asm volatile("mma.sync.aligned.m16n8k16.row.col.f32.bf16.bf16.f32 "
                 "{%0,%1,%2,%3}, {%4,%5,%6,%7}, {%8,%9}, {%0,%1,%2,%3};"
                 : "+f"(c0), "+f"(c1), "+f"(c2), "+f"(c3)
                 : "r"(a0), "r"(a1), "r"(a2), "r"(a3), "r"(b0), "r"(b1));
}

// ---------------- split-bf16 helper ----------------
__device__ __forceinline__ void split_bf16(float x, __nv_bfloat16& h, __nv_bfloat16& l) {
    h = __float2bfloat16_rn(x);
    l = __float2bfloat16_rn(x - __bfloat162float(h));
}

// ---------------- 1a) weight gate-permute + bf16 split: row g*H+h -> 4h+g ----------------
// grid: (4096 rows, 8 matrices), 256 threads
__global__ __launch_bounds__(256) void repack_w_bf16(
    const float* __restrict__ wihf, const float* __restrict__ whhf,
    const float* __restrict__ wihb, const float* __restrict__ whhb)
{
    int p = blockIdx.x;
    int m = blockIdx.y;
    int dir   = m >> 2;
    int typ   = (m >> 1) & 1;              // 0 = ih, 1 = hh
    int layer = m & 1;
    int srow  = (p & 3) * HID + (p >> 2);

    const float* base = dir ? (typ ? whhb : wihb) : (typ ? whhf : wihf);
    const float* src  = base + (size_t)layer * G4 * KDIM;
    __nv_bfloat16* dh = (typ ? g_Whh_h[layer][dir] : g_Wph[layer][dir]) + (size_t)p * KDIM;
    __nv_bfloat16* dl = (typ ? g_Whh_l[layer][dir] : g_Wpl[layer][dir]) + (size_t)p * KDIM;

    int c = threadIdx.x * 4;
    float4 v = *(const float4*)&src[(size_t)srow * KDIM + c];
    __nv_bfloat16 h0, l0, h1, l1, h2, l2, h3, l3;
    split_bf16(v.x, h0, l0); split_bf16(v.y, h1, l1);
    split_bf16(v.z, h2, l2); split_bf16(v.w, h3, l3);
    __nv_bfloat162 hh0 = {h0, h1}, hh1 = {h2, h3};
    __nv_bfloat162 ll0 = {l0, l1}, ll1 = {l2, l3};
    *(__nv_bfloat162*)&dh[c]     = hh0; *(__nv_bfloat162*)&dh[c + 2] = hh1;
    *(__nv_bfloat162*)&dl[c]     = ll0; *(__nv_bfloat162*)&dl[c + 2] = ll1;
}

// ---------------- 1b) fp32 x -> bf16 hi/lo for layer-0 GEMM A ----------------
__global__ __launch_bounds__(256) void conv_x_bf16(const float* __restrict__ x)
{
    size_t i = ((size_t)blockIdx.x * 256 + threadIdx.x) * 4;
    float4 v = *(const float4*)&x[i];
    __nv_bfloat16 h0, l0, h1, l1, h2, l2, h3, l3;
    split_bf16(v.x, h0, l0); split_bf16(v.y, h1, l1);
    split_bf16(v.z, h2, l2); split_bf16(v.w, h3, l3);
    __nv_bfloat162 hh0 = {h0, h1}, hh1 = {h2, h3};
    __nv_bfloat162 ll0 = {l0, l1}, ll1 = {l2, l3};
    *(__nv_bfloat162*)&g_Ah[0][i]     = hh0; *(__nv_bfloat162*)&g_Ah[0][i + 2] = hh1;
    *(__nv_bfloat162*)&g_Al[0][i]     = ll0; *(__nv_bfloat162*)&g_Al[0][i + 2] = ll1;
}

// ---------------- 2) zero recurrent h + barrier vars ----------------
// g_hb16 = 262144 bf16 = 131072 u32.  grid 256 x 512.
__global__ __launch_bounds__(512) void zero_state() {
    int i = blockIdx.x * blockDim.x + threadIdx.x;
    if (i == 0) { g_bar_count = 0u; g_bar_gen = 0u; }
    ((uint32_t*)g_hb16)[i] = 0u;
}

// ---------------- 3) input GEMM via mma.sync bf16 split (unchanged from R4) ----------------
#define GM_SA  40
#define GM_AH  0
#define GM_AL  5120
#define GM_WH  10240
#define GM_WL  12800
#define GM_STG 15360
#define GM_SMEM (2 * GM_STG * 2)

__global__ __launch_bounds__(256, 2) void gemm_mma(int layer)
{
    extern __shared__ __nv_bfloat16 gsm[];

    int tid = threadIdx.x;
    int wid = tid >> 5;
    int lane = tid & 31;
    int dir = blockIdx.z;
    int n0 = blockIdx.x * 64;
    int m0 = blockIdx.y * 128;

    const __nv_bfloat16* Ah = g_Ah[layer == 0 ? 0 : dir];
    const __nv_bfloat16* Al = g_Al[layer == 0 ? 0 : dir];
    const __nv_bfloat16* Wh = g_Wph[layer][dir];
    const __nv_bfloat16* Wl = g_Wpl[layer][dir];

    uint32_t sb = smem_u32(gsm);

    int arow0 = tid >> 2, aq = tid & 3;
    int wrow  = tid >> 2, wq = tid & 3;
    auto stage = [&](int buf, int k0) {
        uint32_t base = sb + buf * GM_STG * 2;
#pragma unroll
        for (int i = 0; i < 2; i++) {
            int row = arow0 + i * 64;
            uint32_t d = base + (row * GM_SA + aq * 8) * 2;
            size_t s = (size_t)(m0 + row) * KDIM + k0 + aq * 8;
            cp16(d + GM_AH * 2, Ah + s);
            cp16(d + GM_AL * 2, Al + s);
        }
        {
            uint32_t d = base + (wrow * GM_SA + wq * 8) * 2;
            size_t s = (size_t)(n0 + wrow) * KDIM + k0 + wq * 8;
            cp16(d + GM_WH * 2, Wh + s);
            cp16(d + GM_WL * 2, Wl + s);
        }
        cp_commit();
    };

    int m0w = (wid >> 1) * 32;
    int n0w = (wid & 1) * 32;
    int a_row = m0w + (lane & 15);
    int a_col = (lane >> 4) * 8;
    int w_n   = n0w + ((lane >> 4) & 1) * 8 + (lane & 7);
    int w_col = ((lane >> 3) & 1) * 8;

    float acc[2][4][4];
#pragma unroll
    for (int mi = 0; mi < 2; mi++)
#pragma unroll
        for (int j = 0; j < 4; j++)
#pragma unroll
            for (int e = 0; e < 4; e++) acc[mi][j][e] = 0.0f;

    stage(0, 0);
    int buf = 0;
#pragma unroll 1
    for (int ch = 0; ch < KDIM / 32; ch++) {
        if (ch < KDIM / 32 - 1) { stage(buf ^ 1, (ch + 1) * 32); cp_wait1(); }
        else                    { cp_wait0(); }
        __syncthreads();
        uint32_t base = sb + buf * GM_STG * 2;
#pragma unroll
        for (int ks = 0; ks < 2; ks++) {
            uint32_t aH[2][4], aL[2][4], wH[2][4], wL[2][4];
#pragma unroll
            for (int mi = 0; mi < 2; mi++) {
                uint32_t ao = base + ((a_row + mi * 16) * GM_SA + ks * 16 + a_col) * 2;
                ldsm_x4(aH[mi][0], aH[mi][1], aH[mi][2], aH[mi][3], ao + GM_AH * 2);
                ldsm_x4(aL[mi][0], aL[mi][1], aL[mi][2], aL[mi][3], ao + GM_AL * 2);
            }
#pragma unroll
            for (int jp = 0; jp < 2; jp++) {
                uint32_t wo = base + ((w_n + jp * 16) * GM_SA + ks * 16 + w_col) * 2;
                ldsm_x4(wH[jp][0], wH[jp][1], wH[jp][2], wH[jp][3], wo + GM_WH * 2);
                ldsm_x4(wL[jp][0], wL[jp][1], wL[jp][2], wL[jp][3], wo + GM_WL * 2);
            }
#pragma unroll
            for (int mi = 0; mi < 2; mi++) {
#pragma unroll
                for (int j = 0; j < 4; j++) {
                    int jp = j >> 1, hi = (j & 1) * 2;
                    float* c = acc[mi][j];
                    mma_bf16(c[0], c[1], c[2], c[3],
                             aH[mi][0], aH[mi][1], aH[mi][2], aH[mi][3],
                             wH[jp][hi], wH[jp][hi + 1]);
                    mma_bf16(c[0], c[1], c[2], c[3],
                             aH[mi][0], aH[mi][1], aH[mi][2], aH[mi][3],
                             wL[jp][hi], wL[jp][hi + 1]);
                    mma_bf16(c[0], c[1], c[2], c[3],
                             aL[mi][0], aL[mi][1], aL[mi][2], aL[mi][3],
                             wH[jp][hi], wH[jp][hi + 1]);
                }
            }
        }
        __syncthreads();
        buf ^= 1;
    }

    float* C = g_xg[dir];
    int g = lane >> 2, q = lane & 3;
#pragma unroll
    for (int mi = 0; mi < 2; mi++) {
        int row = m0 + m0w + mi * 16 + g;
#pragma unroll
        for (int j = 0; j < 4; j++) {
            int col = n0 + n0w + j * 8 + q * 2;
            float2 v0 = { acc[mi][j][0], acc[mi][j][1] };
            float2 v1 = { acc[mi][j][2], acc[mi][j][3] };
            *(float2*)&C[(size_t)row * G4 + col]       = v0;
            *(float2*)&C[(size_t)(row + 8) * G4 + col] = v1;
        }
    }
}

// ---------------- 4) persistent recurrent kernel on tensor cores ----------------
// 128 CTAs: cta -> dir = cta>>6, jt = cta&63 -> gate cols [jt*64, jt*64+64), 16 h.
// Per step: gates[32 b][64 j] = h[32 b][1024 k] @ Whh[j][k]^T via split-bf16 3-term mma.
// Whh-hi resident in SMEM (147KB); Whh-lo + h-hi/lo streamed in k-chunks of 64 (2 bufs).
// SMEM (bytes): Wh 147456 | A 4x4608=18432 | Wl 2x9216=18432 | gates 8192 = 192512.
#define RS_WH   0
#define RS_A    147456
#define RS_WL   165888
#define RS_GT   184320
#define RS_SMEM 192512

__global__ __launch_bounds__(256, 1) void lstm_mma(int layer, float* __restrict__ dout)
{
    extern __shared__ char sm8[];
    uint32_t sb = smem_u32(sm8);
    float* gates_s = (float*)(sm8 + RS_GT);

    int tid  = threadIdx.x;
    int wid  = tid >> 5;
    int lane = tid & 31;
    int cta  = blockIdx.x;
    int d    = cta >> 6;
    int jt   = cta & 63;
    int j0g  = jt * 64;          // gate-column base
    int hbase = jt * 16;         // hidden-index base

    const __nv_bfloat16* WhG = g_Whh_h[layer][d];
    const __nv_bfloat16* WlG = g_Whh_l[layer][d];
    const float* xgb = g_xg[d];
    __nv_bfloat16* hb = g_hb16 + (size_t)d * 2 * 2 * BATCH * HID;  // [pp][prec][b][k]

    // ---- prologue: load resident Whh-hi (16 chunks x 64 rows x 64 k) ----
#pragma unroll 4
    for (int c = 0; c < 32; c++) {
        int idx = tid + c * 256;
        int ck = idx >> 9, rem = idx & 511;
        int r = rem >> 3, q = rem & 7;
        cp16(sb + RS_WH + (uint32_t)(((ck * 64 + r) * 72 + q * 8) * 2),
             WhG + (size_t)(j0g + r) * KDIM + ck * 64 + q * 8);
    }
    cp_commit(); cp_wait0(); __syncthreads();

    // lane-level ldmatrix offsets
    uint32_t w_lane = (uint32_t)(((wid * 8 + (lane & 7)) * 72 + ((lane >> 3) & 1) * 8) * 2);
    uint32_t a_lane = (uint32_t)((((lane & 15)) * 72 + (lane >> 4) * 8) * 2);

    int b = tid & 31;
    int hrow = tid >> 5;        // 0..7
    float c_reg[2] = {0.0f, 0.0f};

    // staging decomposition
    int ar = tid >> 3, aq = (tid & 7) * 8;          // A: rows 0..31
    for (int t = 0; t < SEQ; t++) {
        int time = d ? (SEQ - 1 - t) : t;
        int rp = t & 1, wp = rp ^ 1;
        const __nv_bfloat16* hin_h = hb + (size_t)(rp * 2 + 0) * BATCH * HID;
        const __nv_bfloat16* hin_l = hb + (size_t)(rp * 2 + 1) * BATCH * HID;

        // xg prefetch (pointwise tail)
        float4 xv[2];
#pragma unroll
        for (int it = 0; it < 2; it++) {
            int hl16 = hrow + it * 8;
            xv[it] = *(const float4*)(xgb + (size_t)time * BATCH * G4
                                      + (size_t)b * G4 + j0g + hl16 * 4);
        }

        float acc[2][4];
#pragma unroll
        for (int mi = 0; mi < 2; mi++)
#pragma unroll
            for (int e = 0; e < 4; e++) acc[mi][e] = 0.0f;

        auto stage = [&](int buf, int k0) {
            uint32_t abase = sb + RS_A + buf * 9216;
            cp16(abase +        (uint32_t)((ar * 72 + aq) * 2), hin_h + (size_t)ar * HID + k0 + aq);
            cp16(abase + 4608 + (uint32_t)((ar * 72 + aq) * 2), hin_l + (size_t)ar * HID + k0 + aq);
            uint32_t wbase = sb + RS_WL + buf * 9216;
#pragma unroll
            for (int i = 0; i < 2; i++) {
                int idx = tid + i * 256;
                int r = idx >> 3, q = (idx & 7) * 8;
                cp16(wbase + (uint32_t)((r * 72 + q) * 2),
                     WlG + (size_t)(j0g + r) * KDIM + k0 + q);
            }
            cp_commit();
        };

        stage(0, 0);
        int buf = 0;
#pragma unroll 1
        for (int ch = 0; ch < 16; ch++) {
            if (ch < 15) { stage(buf ^ 1, (ch + 1) * 64); cp_wait1(); }
            else         { cp_wait0(); }
            __syncthreads();
            uint32_t whb = sb + RS_WH + ch * 9216 + w_lane;
            uint32_t wlb = sb + RS_WL + buf * 9216 + w_lane;
            uint32_t ab  = sb + RS_A  + buf * 9216 + a_lane;
#pragma unroll
            for (int ks = 0; ks < 4; ks++) {
                uint32_t aH0[4], aH1[4], aL0[4], aL1[4], bh0, bh1, bl0, bl1;
                ldsm_x4(aH0[0], aH0[1], aH0[2], aH0[3], ab + ks * 32);
                ldsm_x4(aH1[0], aH1[1], aH1[2], aH1[3], ab + 2304 + ks * 32);
                ldsm_x4(aL0[0], aL0[1], aL0[2], aL0[3], ab + 4608 + ks * 32);
                ldsm_x4(aL1[0], aL1[1], aL1[2], aL1[3], ab + 6912 + ks * 32);
                ldsm_x2(bh0, bh1, whb + ks * 32);
                ldsm_x2(bl0, bl1, wlb + ks * 32);
                mma_bf16(acc[0][0], acc[0][1], acc[0][2], acc[0][3],
                         aH0[0], aH0[1], aH0[2], aH0[3], bh0, bh1);
                mma_bf16(acc[0][0], acc[0][1], acc[0][2], acc[0][3],
                         aH0[0], aH0[1], aH0[2], aH0[3], bl0, bl1);
                mma_bf16(acc[0][0], acc[0][1], acc[0][2], acc[0][3],
                         aL0[0], aL0[1], aL0[2], aL0[3], bh0, bh1);
                mma_bf16(acc[1][0], acc[1][1], acc[1][2], acc[1][3],
                         aH1[0], aH1[1], aH1[2], aH1[3], bh0, bh1);
                mma_bf16(acc[1][0], acc[1][1], acc[1][2], acc[1][3],
                         aH1[0], aH1[1], aH1[2], aH1[3], bl0, bl1);
                mma_bf16(acc[1][0], acc[1][1], acc[1][2], acc[1][3],
                         aL1[0], aL1[1], aL1[2], aL1[3], bh0, bh1);
            }
            __syncthreads();
            buf ^= 1;
        }

        // ---- accumulators -> gates_s[b][j] ----
        {
            int g = lane >> 2, q2 = (lane & 3) * 2;
#pragma unroll
            for (int mi = 0; mi < 2; mi++) {
                float2 v0 = { acc[mi][0], acc[mi][1] };
                float2 v1 = { acc[mi][2], acc[mi][3] };
                *(float2*)&gates_s[(mi * 16 + g) * 64 + wid * 8 + q2]     = v0;
                *(float2*)&gates_s[(mi * 16 + g + 8) * 64 + wid * 8 + q2] = v1;
            }
        }
        __syncthreads();

        // ---- pointwise: thread owns (b, hl16) for it=0,1 ----
#pragma unroll
        for (int it = 0; it < 2; it++) {
            int hl16 = hrow + it * 8;
            float4 gq = *(const float4*)&gates_s[b * 64 + hl16 * 4];
            float gi = gq.x + xv[it].x;
            float gf = gq.y + xv[it].y;
            float gg = gq.z + xv[it].z;
            float go = gq.w + xv[it].w;

            float iv = 1.0f / (1.0f + expf(-gi));
            float fv = 1.0f / (1.0f + expf(-gf));
            float gv = tanhf(gg);
            float ov = 1.0f / (1.0f + expf(-go));

            float c = fv * c_reg[it] + iv * gv;
            float hn = ov * tanhf(c);
            c_reg[it] = c;

            int hg = hbase + hl16;
            __nv_bfloat16 hh, hl;
            split_bf16(hn, hh, hl);
            hb[(size_t)(wp * 2 + 0) * BATCH * HID + (size_t)b * HID + hg] = hh;
            hb[(size_t)(wp * 2 + 1) * BATCH * HID + (size_t)b * HID + hg] = hl;

            if (layer == 0) {
                size_t arow = ((size_t)time * BATCH + b) * KDIM + hg;
                g_Ah[d][arow] = hh;
                g_Al[d][arow] = hl;
            } else {
                dout[(size_t)time * BATCH * 2 * HID + (size_t)b * 2 * HID + d * HID + hg] = hn;
            }
            if (time == SEQ - 1) {
                dout[OUT_HALL + (size_t)layer * BATCH * 2 * HID + (size_t)b * 2 * HID + d * HID + hg] = hn;
                dout[OUT_CALL + (size_t)layer * BATCH * 2 * HID + (size_t)b * 2 * HID + d * HID + hg] = c;
            }
        }

        // ---- grid barrier ----
        if (t < SEQ - 1) {
            __syncthreads();
            if (tid == 0) {
                unsigned arr = atom_add_rel(&g_bar_count, 1u);
                if (arr == (unsigned)((t + 1) * NCTA - 1)) {
                    st_rel(&g_bar_gen, (unsigned)(t + 1));
                } else {
                    while (ld_acq(&g_bar_gen) < (unsigned)(t + 1)) { __nanosleep(64); }
                }
            }
            __syncthreads();
        }
    }
}

// ---------------- host launcher ----------------
extern "C" void kernel_launch(void* const* d_in, const int* in_sizes, int n_in,
                              void* d_out, int out_size)
{
    const float* x    = (const float*)d_in[0];
    const float* wihf = (const float*)d_in[1];
    const float* whhf = (const float*)d_in[2];
    const float* wihb = (const float*)d_in[3];
    const float* whhb = (const float*)d_in[4];
    float* out = (float*)d_out;
    (void)in_sizes; (void)n_in; (void)out_size;

    cudaFuncSetAttribute(gemm_mma, cudaFuncAttributeMaxDynamicSharedMemorySize, GM_SMEM);
    cudaFuncSetAttribute(lstm_mma, cudaFuncAttributeMaxDynamicSharedMemorySize, RS_SMEM);

    repack_w_bf16<<<dim3(G4, 8), 256>>>(wihf, whhf, wihb, whhb);
    conv_x_bf16<<<MROWS * KDIM / 1024, 256>>>(x);

    for (int layer = 0; layer < 2; layer++) {
        zero_state<<<256, 512>>>();
        gemm_mma<<<dim3(G4 / 64, MROWS / 128, 2), 256, GM_SMEM>>>(layer);
        lstm_mma<<<NCTA, 256, RS_SMEM>>>(layer, out);
    }
}

// round 6
// speedup vs baseline: 3.3228x; 1.1812x over previous
#include <cuda_runtime.h>
#include <cuda_bf16.h>
#include <cuda_fp16.h>
#include <math.h>
#include <stdint.h>

typedef unsigned long long ull;

// ---------------- problem constants ----------------
#define SEQ   256
#define BATCH 32
#define HID   1024
#define G4    4096
#define KDIM  1024
#define MROWS (SEQ*BATCH)

#define NCTA  128           // persistent grid (2 dirs x 64 j-tiles of 64 gate cols)

// output layout inside d_out (floats)
#define OUT_HALL   (SEQ*BATCH*2*HID)
#define OUT_CALL   (OUT_HALL + 2*BATCH*2*HID)

// ---------------- device scratch ----------------
__device__ float g_xg  [2][SEQ*BATCH*G4];          // per-direction xg
__device__ __nv_bfloat16 g_Wph[2][2][G4*KDIM];     // gate-permuted W_ih hi (input GEMM)
__device__ __nv_bfloat16 g_Wpl[2][2][G4*KDIM];     // gate-permuted W_ih lo
__device__ __half        g_Whh16[2][2][G4*KDIM];   // gate-permuted W_hh, single fp16 (recurrence)
__device__ __nv_bfloat16 g_Ah[2][MROWS*KDIM];      // GEMM A hi ([0]=x layer0, [dir] layer1)
__device__ __nv_bfloat16 g_Al[2][MROWS*KDIM];      // GEMM A lo
__device__ __half        g_h16[2*2*2*BATCH*HID];   // [dir][pp][hi/lo][b][k] recurrent h fp16
__device__ unsigned g_bar_count;
__device__ unsigned g_bar_gen;

// ---------------- sync / async-copy helpers ----------------
__device__ __forceinline__ unsigned ld_acq(const unsigned* p) {
    unsigned v; asm volatile("ld.acquire.gpu.u32 %0, [%1];" : "=r"(v) : "l"(p) : "memory"); return v;
}
__device__ __forceinline__ void st_rel(unsigned* p, unsigned v) {
    asm volatile("st.release.gpu.u32 [%0], %1;" :: "l"(p), "r"(v) : "memory");
}
__device__ __forceinline__ unsigned atom_add_rel(unsigned* p, unsigned v) {
    unsigned o; asm volatile("atom.release.gpu.add.u32 %0, [%1], %2;"
                             : "=r"(o) : "l"(p), "r"(v) : "memory"); return o;
}
__device__ __forceinline__ void cp16(uint32_t s, const void* g) {
    asm volatile("cp.async.cg.shared.global [%0], [%1], 16;" :: "r"(s), "l"(g));
}
__device__ __forceinline__ void cp_commit() { asm volatile("cp.async.commit_group;"); }
__device__ __forceinline__ void cp_wait1()  { asm volatile("cp.async.wait_group 1;" ::: "memory"); }
__device__ __forceinline__ void cp_wait0()  { asm volatile("cp.async.wait_group 0;" ::: "memory"); }

__device__ __forceinline__ uint32_t smem_u32(const void* p) {
    return (uint32_t)__cvta_generic_to_shared(p);
}

// ---------------- mma.sync / ldmatrix helpers (base PTX, sm_80+) ----------------
__device__ __forceinline__ void ldsm_x4(uint32_t& r0, uint32_t& r1, uint32_t& r2, uint32_t& r3,
                                        uint32_t addr) {
    asm volatile("ldmatrix.sync.aligned.m8n8.x4.shared.b16 {%0,%1,%2,%3}, [%4];"
                 : "=r"(r0), "=r"(r1), "=r"(r2), "=r"(r3) : "r"(addr));
}
__device__ __forceinline__ void ldsm_x2(uint32_t& r0, uint32_t& r1, uint32_t addr) {
    asm volatile("ldmatrix.sync.aligned.m8n8.x2.shared.b16 {%0,%1}, [%2];"
                 : "=r"(r0), "=r"(r1) : "r"(addr));
}
__device__ __forceinline__ void mma_bf16(float& c0, float& c1, float& c2, float& c3,
                                         uint32_t a0, uint32_t a1, uint32_t a2, uint32_t a3,
                                         uint32_t b0, uint32_t b1) {
    asm volatile("mma.sync.aligned.m16n8k16.row.col.f32.bf16.bf16.f32 "
                 "{%0,%1,%2,%3}, {%4,%5,%6,%7}, {%8,%9}, {%0,%1,%2,%3};"
                 : "+f"(c0), "+f"(c1), "+f"(c2), "+f"(c3)
                 : "r"(a0), "r"(a1), "r"(a2), "r"(a3), "r"(b0), "r"(b1));
}
__device__ __forceinline__ void mma_f16(float& c0, float& c1, float& c2, float& c3,
                                        uint32_t a0, uint32_t a1, uint32_t a2, uint32_t a3,
                                        uint32_t b0, uint32_t b1) {
    asm volatile("mma.sync.aligned.m16n8k16.row.col.f32.f16.f16.f32 "
                 "{%0,%1,%2,%3}, {%4,%5,%6,%7}, {%8,%9}, {%0,%1,%2,%3};"
                 : "+f"(c0), "+f"(c1), "+f"(c2), "+f"(c3)
                 : "r"(a0), "r"(a1), "r"(a2), "r"(a3), "r"(b0), "r"(b1));
}

// ---------------- split helpers ----------------
__device__ __forceinline__ void split_bf16(float x, __nv_bfloat16& h, __nv_bfloat16& l) {
    h = __float2bfloat16_rn(x);
    l = __float2bfloat16_rn(x - __bfloat162float(h));
}
__device__ __forceinline__ void split_f16(float x, __half& h, __half& l) {
    h = __float2half_rn(x);
    l = __float2half_rn(x - __half2float(h));
}

// ---------------- 1a) weight gate-permute: row g*H+h -> 4h+g ----------------
// typ 0 (W_ih): bf16 hi/lo split. typ 1 (W_hh): single fp16.
__global__ __launch_bounds__(256) void repack_w(
    const float* __restrict__ wihf, const float* __restrict__ whhf,
    const float* __restrict__ wihb, const float* __restrict__ whhb)
{
    int p = blockIdx.x;
    int m = blockIdx.y;
    int dir   = m >> 2;
    int typ   = (m >> 1) & 1;
    int layer = m & 1;
    int srow  = (p & 3) * HID + (p >> 2);

    const float* base = dir ? (typ ? whhb : wihb) : (typ ? whhf : wihf);
    const float* src  = base + (size_t)layer * G4 * KDIM;

    int c = threadIdx.x * 4;
    float4 v = *(const float4*)&src[(size_t)srow * KDIM + c];

    if (typ) {
        __half* dst = g_Whh16[layer][dir] + (size_t)p * KDIM;
        __half2 a = {__float2half_rn(v.x), __float2half_rn(v.y)};
        __half2 b = {__float2half_rn(v.z), __float2half_rn(v.w)};
        *(__half2*)&dst[c]     = a;
        *(__half2*)&dst[c + 2] = b;
    } else {
        __nv_bfloat16* dh = g_Wph[layer][dir] + (size_t)p * KDIM;
        __nv_bfloat16* dl = g_Wpl[layer][dir] + (size_t)p * KDIM;
        __nv_bfloat16 h0, l0, h1, l1, h2, l2, h3, l3;
        split_bf16(v.x, h0, l0); split_bf16(v.y, h1, l1);
        split_bf16(v.z, h2, l2); split_bf16(v.w, h3, l3);
        __nv_bfloat162 hh0 = {h0, h1}, hh1 = {h2, h3};
        __nv_bfloat162 ll0 = {l0, l1}, ll1 = {l2, l3};
        *(__nv_bfloat162*)&dh[c]     = hh0; *(__nv_bfloat162*)&dh[c + 2] = hh1;
        *(__nv_bfloat162*)&dl[c]     = ll0; *(__nv_bfloat162*)&dl[c + 2] = ll1;
    }
}

// ---------------- 1b) fp32 x -> bf16 hi/lo for layer-0 GEMM A ----------------
__global__ __launch_bounds__(256) void conv_x_bf16(const float* __restrict__ x)
{
    size_t i = ((size_t)blockIdx.x * 256 + threadIdx.x) * 4;
    float4 v = *(const float4*)&x[i];
    __nv_bfloat16 h0, l0, h1, l1, h2, l2, h3, l3;
    split_bf16(v.x, h0, l0); split_bf16(v.y, h1, l1);
    split_bf16(v.z, h2, l2); split_bf16(v.w, h3, l3);
    __nv_bfloat162 hh0 = {h0, h1}, hh1 = {h2, h3};
    __nv_bfloat162 ll0 = {l0, l1}, ll1 = {l2, l3};
    *(__nv_bfloat162*)&g_Ah[0][i]     = hh0; *(__nv_bfloat162*)&g_Ah[0][i + 2] = hh1;
    *(__nv_bfloat162*)&g_Al[0][i]     = ll0; *(__nv_bfloat162*)&g_Al[0][i + 2] = ll1;
}

// ---------------- 2) zero recurrent h + barrier vars ----------------
// g_h16 = 262144 halves = 131072 u32.  grid 256 x 512.
__global__ __launch_bounds__(512) void zero_state() {
    int i = blockIdx.x * blockDim.x + threadIdx.x;
    if (i == 0) { g_bar_count = 0u; g_bar_gen = 0u; }
    ((uint32_t*)g_h16)[i] = 0u;
}

// ---------------- 3) input GEMM via mma.sync bf16 split (unchanged from R5) ----------------
#define GM_SA  40
#define GM_AH  0
#define GM_AL  5120
#define GM_WH  10240
#define GM_WL  12800
#define GM_STG 15360
#define GM_SMEM (2 * GM_STG * 2)

__global__ __launch_bounds__(256, 2) void gemm_mma(int layer)
{
    extern __shared__ __nv_bfloat16 gsm[];

    int tid = threadIdx.x;
    int wid = tid >> 5;
    int lane = tid & 31;
    int dir = blockIdx.z;
    int n0 = blockIdx.x * 64;
    int m0 = blockIdx.y * 128;

    const __nv_bfloat16* Ah = g_Ah[layer == 0 ? 0 : dir];
    const __nv_bfloat16* Al = g_Al[layer == 0 ? 0 : dir];
    const __nv_bfloat16* Wh = g_Wph[layer][dir];
    const __nv_bfloat16* Wl = g_Wpl[layer][dir];

    uint32_t sb = smem_u32(gsm);

    int arow0 = tid >> 2, aq = tid & 3;
    int wrow  = tid >> 2, wq = tid & 3;
    auto stage = [&](int buf, int k0) {
        uint32_t base = sb + buf * GM_STG * 2;
#pragma unroll
        for (int i = 0; i < 2; i++) {
            int row = arow0 + i * 64;
            uint32_t d = base + (row * GM_SA + aq * 8) * 2;
            size_t s = (size_t)(m0 + row) * KDIM + k0 + aq * 8;
            cp16(d + GM_AH * 2, Ah + s);
            cp16(d + GM_AL * 2, Al + s);
        }
        {
            uint32_t d = base + (wrow * GM_SA + wq * 8) * 2;
            size_t s = (size_t)(n0 + wrow) * KDIM + k0 + wq * 8;
            cp16(d + GM_WH * 2, Wh + s);
            cp16(d + GM_WL * 2, Wl + s);
        }
        cp_commit();
    };

    int m0w = (wid >> 1) * 32;
    int n0w = (wid & 1) * 32;
    int a_row = m0w + (lane & 15);
    int a_col = (lane >> 4) * 8;
    int w_n   = n0w + ((lane >> 4) & 1) * 8 + (lane & 7);
    int w_col = ((lane >> 3) & 1) * 8;

    float acc[2][4][4];
#pragma unroll
    for (int mi = 0; mi < 2; mi++)
#pragma unroll
        for (int j = 0; j < 4; j++)
#pragma unroll
            for (int e = 0; e < 4; e++) acc[mi][j][e] = 0.0f;

    stage(0, 0);
    int buf = 0;
#pragma unroll 1
    for (int ch = 0; ch < KDIM / 32; ch++) {
        if (ch < KDIM / 32 - 1) { stage(buf ^ 1, (ch + 1) * 32); cp_wait1(); }
        else                    { cp_wait0(); }
        __syncthreads();
        uint32_t base = sb + buf * GM_STG * 2;
#pragma unroll
        for (int ks = 0; ks < 2; ks++) {
            uint32_t aH[2][4], aL[2][4], wH[2][4], wL[2][4];
#pragma unroll
            for (int mi = 0; mi < 2; mi++) {
                uint32_t ao = base + ((a_row + mi * 16) * GM_SA + ks * 16 + a_col) * 2;
                ldsm_x4(aH[mi][0], aH[mi][1], aH[mi][2], aH[mi][3], ao + GM_AH * 2);
                ldsm_x4(aL[mi][0], aL[mi][1], aL[mi][2], aL[mi][3], ao + GM_AL * 2);
            }
#pragma unroll
            for (int jp = 0; jp < 2; jp++) {
                uint32_t wo = base + ((w_n + jp * 16) * GM_SA + ks * 16 + w_col) * 2;
                ldsm_x4(wH[jp][0], wH[jp][1], wH[jp][2], wH[jp][3], wo + GM_WH * 2);
                ldsm_x4(wL[jp][0], wL[jp][1], wL[jp][2], wL[jp][3], wo + GM_WL * 2);
            }
#pragma unroll
            for (int mi = 0; mi < 2; mi++) {
#pragma unroll
                for (int j = 0; j < 4; j++) {
                    int jp = j >> 1, hi = (j & 1) * 2;
                    float* c = acc[mi][j];
                    mma_bf16(c[0], c[1], c[2], c[3],
                             aH[mi][0], aH[mi][1], aH[mi][2], aH[mi][3],
                             wH[jp][hi], wH[jp][hi + 1]);
                    mma_bf16(c[0], c[1], c[2], c[3],
                             aH[mi][0], aH[mi][1], aH[mi][2], aH[mi][3],
                             wL[jp][hi], wL[jp][hi + 1]);
                    mma_bf16(c[0], c[1], c[2], c[3],
                             aL[mi][0], aL[mi][1], aL[mi][2], aL[mi][3],
                             wH[jp][hi], wH[jp][hi + 1]);
                }
            }
        }
        __syncthreads();
        buf ^= 1;
    }

    float* C = g_xg[dir];
    int g = lane >> 2, q = lane & 3;
#pragma unroll
    for (int mi = 0; mi < 2; mi++) {
        int row = m0 + m0w + mi * 16 + g;
#pragma unroll
        for (int j = 0; j < 4; j++) {
            int col = n0 + n0w + j * 8 + q * 2;
            float2 v0 = { acc[mi][j][0], acc[mi][j][1] };
            float2 v1 = { acc[mi][j][2], acc[mi][j][3] };
            *(float2*)&C[(size_t)row * G4 + col]       = v0;
            *(float2*)&C[(size_t)(row + 8) * G4 + col] = v1;
        }
    }
}

// ---------------- 4) persistent recurrent kernel: fp16, W resident, 2-term ----------------
// 128 CTAs: dir = cta>>6, jt = cta&63 -> gate cols [jt*64, +64) = 16 hidden.
// gates[32b][64j] = h_hi[32,1024] @ W^T + h_lo[32,1024] @ W^T, fp16 in, fp32 accum.
// W fp16 resident in SMEM (144KB, chunked [k64-chunk][64 rows][72]).
// h hi/lo streamed per step in 4 k-chunks of 256, double-buffered.
// SMEM: W 147456 | A 2 x 33792 | gates 8192 = 223232 bytes.
#define RS_WH   0
#define RS_A    147456
#define RS_ABUF 33792
#define RS_ALO  16896
#define RS_GT   (RS_A + 2 * RS_ABUF)     // 215040
#define RS_SMEM (RS_GT + 8192)           // 223232

__global__ __launch_bounds__(256, 1) void lstm_f16(int layer, float* __restrict__ dout)
{
    extern __shared__ char sm8[];
    uint32_t sb = smem_u32(sm8);
    float* gates_s = (float*)(sm8 + RS_GT);

    int tid  = threadIdx.x;
    int wid  = tid >> 5;
    int lane = tid & 31;
    int cta  = blockIdx.x;
    int d    = cta >> 6;
    int jt   = cta & 63;
    int j0g  = jt * 64;
    int hbase = jt * 16;

    const __half* WhG = g_Whh16[layer][d];
    const float* xgb = g_xg[d];
    __half* hb = g_h16 + (size_t)d * 2 * 2 * BATCH * HID;   // [pp][prec][b][k]

    // ---- prologue: load resident W (16 chunks x 64 rows x 64 k, stride-72 rows) ----
#pragma unroll 4
    for (int c = 0; c < 32; c++) {
        int idx = tid + c * 256;
        int ck = idx >> 9, rem = idx & 511;
        int r = rem >> 3, q = rem & 7;
        cp16(sb + RS_WH + (uint32_t)(((ck * 64 + r) * 72 + q * 8) * 2),
             WhG + (size_t)(j0g + r) * KDIM + ck * 64 + q * 8);
    }
    cp_commit(); cp_wait0(); __syncthreads();

    uint32_t w_lane = (uint32_t)(((wid * 8 + (lane & 7)) * 72 + ((lane >> 3) & 1) * 8) * 2);
    uint32_t a_lane = (uint32_t)(((lane & 15) * 264 + (lane >> 4) * 8) * 2);

    int b = tid & 31;
    int hrow = tid >> 5;          // 0..7
    float c_reg[2] = {0.0f, 0.0f};

    int s_row = tid >> 5, s_q = tid & 31;   // staging: idx = tid + i*256 -> row idx>>5, q idx&31

    for (int t = 0; t < SEQ; t++) {
        int time = d ? (SEQ - 1 - t) : t;
        int rp = t & 1, wp = rp ^ 1;
        const __half* hin_h = hb + (size_t)(rp * 2 + 0) * BATCH * HID;
        const __half* hin_l = hb + (size_t)(rp * 2 + 1) * BATCH * HID;

        // xg prefetch for the pointwise tail
        float4 xv[2];
#pragma unroll
        for (int it = 0; it < 2; it++) {
            int hl16 = hrow + it * 8;
            xv[it] = *(const float4*)(xgb + (size_t)time * BATCH * G4
                                      + (size_t)b * G4 + j0g + hl16 * 4);
        }

        float acc[2][4];
#pragma unroll
        for (int mi = 0; mi < 2; mi++)
#pragma unroll
            for (int e = 0; e < 4; e++) acc[mi][e] = 0.0f;

        // stage one k=256 chunk of h hi/lo
        auto stage = [&](int bf, int k0) {
            uint32_t base = sb + RS_A + bf * RS_ABUF;
#pragma unroll
            for (int i = 0; i < 4; i++) {
                int row = s_row + i * 8;
                uint32_t off = (uint32_t)(row * 528 + s_q * 16);
                cp16(base + off,          hin_h + (size_t)row * HID + k0 + s_q * 8);
                cp16(base + RS_ALO + off, hin_l + (size_t)row * HID + k0 + s_q * 8);
            }
            cp_commit();
        };

        stage(0, 0);
        int bf = 0;
#pragma unroll 1
        for (int ch = 0; ch < 4; ch++) {
            if (ch < 3) { stage(bf ^ 1, (ch + 1) * 256); cp_wait1(); }
            else        { cp_wait0(); }
            __syncthreads();
            uint32_t ab = sb + RS_A + bf * RS_ABUF + a_lane;
#pragma unroll
            for (int ks = 0; ks < 16; ks++) {
                int kk = ch * 16 + ks;
                uint32_t wa = sb + RS_WH + (kk >> 2) * 9216 + (kk & 3) * 32 + w_lane;
                uint32_t aH0[4], aH1[4], aL0[4], aL1[4], b0, b1;
                ldsm_x4(aH0[0], aH0[1], aH0[2], aH0[3], ab + ks * 32);
                ldsm_x4(aH1[0], aH1[1], aH1[2], aH1[3], ab + 8448 + ks * 32);
                ldsm_x4(aL0[0], aL0[1], aL0[2], aL0[3], ab + RS_ALO + ks * 32);
                ldsm_x4(aL1[0], aL1[1], aL1[2], aL1[3], ab + RS_ALO + 8448 + ks * 32);
                ldsm_x2(b0, b1, wa);
                mma_f16(acc[0][0], acc[0][1], acc[0][2], acc[0][3],
                        aH0[0], aH0[1], aH0[2], aH0[3], b0, b1);
                mma_f16(acc[0][0], acc[0][1], acc[0][2], acc[0][3],
                        aL0[0], aL0[1], aL0[2], aL0[3], b0, b1);
                mma_f16(acc[1][0], acc[1][1], acc[1][2], acc[1][3],
                        aH1[0], aH1[1], aH1[2], aH1[3], b0, b1);
                mma_f16(acc[1][0], acc[1][1], acc[1][2], acc[1][3],
                        aL1[0], aL1[1], aL1[2], aL1[3], b0, b1);
            }
            __syncthreads();
            bf ^= 1;
        }

        // ---- accumulators -> gates_s[b][j] ----
        {
            int g = lane >> 2, q2 = (lane & 3) * 2;
#pragma unroll
            for (int mi = 0; mi < 2; mi++) {
                float2 v0 = { acc[mi][0], acc[mi][1] };
                float2 v1 = { acc[mi][2], acc[mi][3] };
                *(float2*)&gates_s[(mi * 16 + g) * 64 + wid * 8 + q2]     = v0;
                *(float2*)&gates_s[(mi * 16 + g + 8) * 64 + wid * 8 + q2] = v1;
            }
        }
        __syncthreads();

        // ---- pointwise: thread owns (b, hl16) for it=0,1 ----
#pragma unroll
        for (int it = 0; it < 2; it++) {
            int hl16 = hrow + it * 8;
            float4 gq = *(const float4*)&gates_s[b * 64 + hl16 * 4];
            float gi = gq.x + xv[it].x;
            float gf = gq.y + xv[it].y;
            float gg = gq.z + xv[it].z;
            float go = gq.w + xv[it].w;

            float iv = 1.0f / (1.0f + expf(-gi));
            float fv = 1.0f / (1.0f + expf(-gf));
            float gv = tanhf(gg);
            float ov = 1.0f / (1.0f + expf(-go));

            float c = fv * c_reg[it] + iv * gv;
            float hn = ov * tanhf(c);
            c_reg[it] = c;

            int hg = hbase + hl16;
            __half hh, hl;
            split_f16(hn, hh, hl);
            hb[(size_t)(wp * 2 + 0) * BATCH * HID + (size_t)b * HID + hg] = hh;
            hb[(size_t)(wp * 2 + 1) * BATCH * HID + (size_t)b * HID + hg] = hl;

            if (layer == 0) {
                size_t arow = ((size_t)time * BATCH + b) * KDIM + hg;
                __nv_bfloat16 bh, bl;
                split_bf16(hn, bh, bl);
                g_Ah[d][arow] = bh;
                g_Al[d][arow] = bl;
            } else {
                dout[(size_t)time * BATCH * 2 * HID + (size_t)b * 2 * HID + d * HID + hg] = hn;
            }
            if (time == SEQ - 1) {
                dout[OUT_HALL + (size_t)layer * BATCH * 2 * HID + (size_t)b * 2 * HID + d * HID + hg] = hn;
                dout[OUT_CALL + (size_t)layer * BATCH * 2 * HID + (size_t)b * 2 * HID + d * HID + hg] = c;
            }
        }

        // ---- grid barrier ----
        if (t < SEQ - 1) {
            __syncthreads();
            if (tid == 0) {
                unsigned arr = atom_add_rel(&g_bar_count, 1u);
                if (arr == (unsigned)((t + 1) * NCTA - 1)) {
                    st_rel(&g_bar_gen, (unsigned)(t + 1));
                } else {
                    while (ld_acq(&g_bar_gen) < (unsigned)(t + 1)) { __nanosleep(64); }
                }
            }
            __syncthreads();
        }
    }
}

// ---------------- host launcher ----------------
extern "C" void kernel_launch(void* const* d_in, const int* in_sizes, int n_in,
                              void* d_out, int out_size)
{
    const float* x    = (const float*)d_in[0];
    const float* wihf = (const float*)d_in[1];
    const float* whhf = (const float*)d_in[2];
    const float* wihb = (const float*)d_in[3];
    const float* whhb = (const float*)d_in[4];
    float* out = (float*)d_out;
    (void)in_sizes; (void)n_in; (void)out_size;

    cudaFuncSetAttribute(gemm_mma, cudaFuncAttributeMaxDynamicSharedMemorySize, GM_SMEM);
    cudaFuncSetAttribute(lstm_f16, cudaFuncAttributeMaxDynamicSharedMemorySize, RS_SMEM);

    repack_w<<<dim3(G4, 8), 256>>>(wihf, whhf, wihb, whhb);
    conv_x_bf16<<<MROWS * KDIM / 1024, 256>>>(x);

    for (int layer = 0; layer < 2; layer++) {
        zero_state<<<256, 512>>>();
        gemm_mma<<<dim3(G4 / 64, MROWS / 128, 2), 256, GM_SMEM>>>(layer);
        lstm_f16<<<NCTA, 256, RS_SMEM>>>(layer, out);
    }
}

// round 7
// speedup vs baseline: 4.5715x; 1.3758x over previous
#include <cuda_runtime.h>
#include <cuda_fp16.h>
#include <math.h>
#include <stdint.h>

// ---------------- problem constants ----------------
#define SEQ   256
#define BATCH 32
#define HID   1024
#define G4    4096
#define KDIM  1024
#define MROWS (SEQ*BATCH)

#define NCTA  128           // persistent grid (2 dirs x 64 j-tiles of 64 gate cols)

// output layout inside d_out (floats)
#define OUT_HALL   (SEQ*BATCH*2*HID)
#define OUT_CALL   (OUT_HALL + 2*BATCH*2*HID)

// ---------------- device scratch ----------------
__device__ float  g_xg  [2][SEQ*BATCH*G4];       // per-direction xg
__device__ __half g_Wih16[2][2][G4*KDIM];        // gate-permuted W_ih fp16 (input GEMM)
__device__ __half g_Whh16[2][2][G4*KDIM];        // gate-permuted W_hh fp16 (recurrence)
__device__ __half g_Axh[2][MROWS*KDIM];          // GEMM A hi ([0]=x layer0, [dir] layer1)
__device__ __half g_Axl[2][MROWS*KDIM];          // GEMM A lo
__device__ __half g_h16[2*2*BATCH*HID];          // [dir][pp][b][k] recurrent h fp16
__device__ unsigned g_bar_count;
__device__ unsigned g_bar_gen;

// ---------------- sync / async-copy helpers ----------------
__device__ __forceinline__ unsigned ld_acq(const unsigned* p) {
    unsigned v; asm volatile("ld.acquire.gpu.u32 %0, [%1];" : "=r"(v) : "l"(p) : "memory"); return v;
}
__device__ __forceinline__ void st_rel(unsigned* p, unsigned v) {
    asm volatile("st.release.gpu.u32 [%0], %1;" :: "l"(p), "r"(v) : "memory");
}
__device__ __forceinline__ unsigned atom_add_rel(unsigned* p, unsigned v) {
    unsigned o; asm volatile("atom.release.gpu.add.u32 %0, [%1], %2;"
                             : "=r"(o) : "l"(p), "r"(v) : "memory"); return o;
}
__device__ __forceinline__ void cp16(uint32_t s, const void* g) {
    asm volatile("cp.async.cg.shared.global [%0], [%1], 16;" :: "r"(s), "l"(g));
}
__device__ __forceinline__ void cp_commit() { asm volatile("cp.async.commit_group;"); }
__device__ __forceinline__ void cp_wait1()  { asm volatile("cp.async.wait_group 1;" ::: "memory"); }
__device__ __forceinline__ void cp_wait0()  { asm volatile("cp.async.wait_group 0;" ::: "memory"); }

__device__ __forceinline__ uint32_t smem_u32(const void* p) {
    return (uint32_t)__cvta_generic_to_shared(p);
}

// ---------------- mma.sync / ldmatrix helpers (base PTX, sm_80+) ----------------
__device__ __forceinline__ void ldsm_x4(uint32_t& r0, uint32_t& r1, uint32_t& r2, uint32_t& r3,
                                        uint32_t addr) {
    asm volatile("ldmatrix.sync.aligned.m8n8.x4.shared.b16 {%0,%1,%2,%3}, [%4];"
                 : "=r"(r0), "=r"(r1), "=r"(r2), "=r"(r3) : "r"(addr));
}
__device__ __forceinline__ void ldsm_x2(uint32_t& r0, uint32_t& r1, uint32_t addr) {
    asm volatile("ldmatrix.sync.aligned.m8n8.x2.shared.b16 {%0,%1}, [%2];"
                 : "=r"(r0), "=r"(r1) : "r"(addr));
}
__device__ __forceinline__ void mma_f16(float& c0, float& c1, float& c2, float& c3,
                                        uint32_t a0, uint32_t a1, uint32_t a2, uint32_t a3,
                                        uint32_t b0, uint32_t b1) {
    asm volatile("mma.sync.aligned.m16n8k16.row.col.f32.f16.f16.f32 "
                 "{%0,%1,%2,%3}, {%4,%5,%6,%7}, {%8,%9}, {%0,%1,%2,%3};"
                 : "+f"(c0), "+f"(c1), "+f"(c2), "+f"(c3)
                 : "r"(a0), "r"(a1), "r"(a2), "r"(a3), "r"(b0), "r"(b1));
}

// ---------------- split helper ----------------
__device__ __forceinline__ void split_f16(float x, __half& h, __half& l) {
    h = __float2half_rn(x);
    l = __float2half_rn(x - __half2float(h));
}

// ---------------- 1a) weight gate-permute to fp16: row g*H+h -> 4h+g ----------------
__global__ __launch_bounds__(256) void repack_w(
    const float* __restrict__ wihf, const float* __restrict__ whhf,
    const float* __restrict__ wihb, const float* __restrict__ whhb)
{
    int p = blockIdx.x;
    int m = blockIdx.y;
    int dir   = m >> 2;
    int typ   = (m >> 1) & 1;          // 0 = ih, 1 = hh
    int layer = m & 1;
    int srow  = (p & 3) * HID + (p >> 2);

    const float* base = dir ? (typ ? whhb : wihb) : (typ ? whhf : wihf);
    const float* src  = base + (size_t)layer * G4 * KDIM;
    __half* dst = (typ ? g_Whh16[layer][dir] : g_Wih16[layer][dir]) + (size_t)p * KDIM;

    int c = threadIdx.x * 4;
    float4 v = *(const float4*)&src[(size_t)srow * KDIM + c];
    __half2 a = {__float2half_rn(v.x), __float2half_rn(v.y)};
    __half2 b = {__float2half_rn(v.z), __float2half_rn(v.w)};
    *(__half2*)&dst[c]     = a;
    *(__half2*)&dst[c + 2] = b;
}

// ---------------- 1b) fp32 x -> fp16 hi/lo for layer-0 GEMM A ----------------
__global__ __launch_bounds__(256) void conv_x_f16(const float* __restrict__ x)
{
    size_t i = ((size_t)blockIdx.x * 256 + threadIdx.x) * 4;
    float4 v = *(const float4*)&x[i];
    __half h0, l0, h1, l1, h2, l2, h3, l3;
    split_f16(v.x, h0, l0); split_f16(v.y, h1, l1);
    split_f16(v.z, h2, l2); split_f16(v.w, h3, l3);
    __half2 hh0 = {h0, h1}, hh1 = {h2, h3};
    __half2 ll0 = {l0, l1}, ll1 = {l2, l3};
    *(__half2*)&g_Axh[0][i]     = hh0; *(__half2*)&g_Axh[0][i + 2] = hh1;
    *(__half2*)&g_Axl[0][i]     = ll0; *(__half2*)&g_Axl[0][i + 2] = ll1;
}

// ---------------- 2) zero recurrent h + barrier vars ----------------
// g_h16 = 131072 halves = 65536 u32.  grid 128 x 512.
__global__ __launch_bounds__(512) void zero_state() {
    int i = blockIdx.x * blockDim.x + threadIdx.x;
    if (i == 0) { g_bar_count = 0u; g_bar_gen = 0u; }
    ((uint32_t*)g_h16)[i] = 0u;
}

// ---------------- 3) input GEMM: fp16 2-term (A split hi/lo, W single) ----------------
// C[m][n] = sum_k A[m][k]*W[n][k] as Ah*W + Al*W, fp32 accum.
// BM=128, BN=64, BK=32. 8 warps (4m x 2n), warp tile 32x32.
#define GM_SA  40
#define GM_AH  0
#define GM_AL  5120
#define GM_WH  10240
#define GM_STG 12800
#define GM_SMEM (2 * GM_STG * 2)

__global__ __launch_bounds__(256, 2) void gemm_mma(int layer)
{
    extern __shared__ __half gsm[];

    int tid = threadIdx.x;
    int wid = tid >> 5;
    int lane = tid & 31;
    int dir = blockIdx.z;
    int n0 = blockIdx.x * 64;
    int m0 = blockIdx.y * 128;

    const __half* Ah = g_Axh[layer == 0 ? 0 : dir];
    const __half* Al = g_Axl[layer == 0 ? 0 : dir];
    const __half* W  = g_Wih16[layer][dir];

    uint32_t sb = smem_u32(gsm);

    int arow0 = tid >> 2, aq = tid & 3;
    int wrow  = tid >> 2, wq = tid & 3;
    auto stage = [&](int buf, int k0) {
        uint32_t base = sb + buf * GM_STG * 2;
#pragma unroll
        for (int i = 0; i < 2; i++) {
            int row = arow0 + i * 64;
            uint32_t d = base + (row * GM_SA + aq * 8) * 2;
            size_t s = (size_t)(m0 + row) * KDIM + k0 + aq * 8;
            cp16(d + GM_AH * 2, Ah + s);
            cp16(d + GM_AL * 2, Al + s);
        }
        {
            uint32_t d = base + (wrow * GM_SA + wq * 8) * 2;
            size_t s = (size_t)(n0 + wrow) * KDIM + k0 + wq * 8;
            cp16(d + GM_WH * 2, W + s);
        }
        cp_commit();
    };

    int m0w = (wid >> 1) * 32;
    int n0w = (wid & 1) * 32;
    int a_row = m0w + (lane & 15);
    int a_col = (lane >> 4) * 8;
    int w_n   = n0w + ((lane >> 4) & 1) * 8 + (lane & 7);
    int w_col = ((lane >> 3) & 1) * 8;

    float acc[2][4][4];
#pragma unroll
    for (int mi = 0; mi < 2; mi++)
#pragma unroll
        for (int j = 0; j < 4; j++)
#pragma unroll
            for (int e = 0; e < 4; e++) acc[mi][j][e] = 0.0f;

    stage(0, 0);
    int buf = 0;
#pragma unroll 1
    for (int ch = 0; ch < KDIM / 32; ch++) {
        if (ch < KDIM / 32 - 1) { stage(buf ^ 1, (ch + 1) * 32); cp_wait1(); }
        else                    { cp_wait0(); }
        __syncthreads();
        uint32_t base = sb + buf * GM_STG * 2;
#pragma unroll
        for (int ks = 0; ks < 2; ks++) {
            uint32_t aH[2][4], aL[2][4], wH[2][4];
#pragma unroll
            for (int mi = 0; mi < 2; mi++) {
                uint32_t ao = base + ((a_row + mi * 16) * GM_SA + ks * 16 + a_col) * 2;
                ldsm_x4(aH[mi][0], aH[mi][1], aH[mi][2], aH[mi][3], ao + GM_AH * 2);
                ldsm_x4(aL[mi][0], aL[mi][1], aL[mi][2], aL[mi][3], ao + GM_AL * 2);
            }
#pragma unroll
            for (int jp = 0; jp < 2; jp++) {
                uint32_t wo = base + ((w_n + jp * 16) * GM_SA + ks * 16 + w_col) * 2;
                ldsm_x4(wH[jp][0], wH[jp][1], wH[jp][2], wH[jp][3], wo + GM_WH * 2);
            }
#pragma unroll
            for (int mi = 0; mi < 2; mi++) {
#pragma unroll
                for (int j = 0; j < 4; j++) {
                    int jp = j >> 1, hi = (j & 1) * 2;
                    float* c = acc[mi][j];
                    mma_f16(c[0], c[1], c[2], c[3],
                            aH[mi][0], aH[mi][1], aH[mi][2], aH[mi][3],
                            wH[jp][hi], wH[jp][hi + 1]);
                    mma_f16(c[0], c[1], c[2], c[3],
                            aL[mi][0], aL[mi][1], aL[mi][2], aL[mi][3],
                            wH[jp][hi], wH[jp][hi + 1]);
                }
            }
        }
        __syncthreads();
        buf ^= 1;
    }

    float* C = g_xg[dir];
    int g = lane >> 2, q = lane & 3;
#pragma unroll
    for (int mi = 0; mi < 2; mi++) {
        int row = m0 + m0w + mi * 16 + g;
#pragma unroll
        for (int j = 0; j < 4; j++) {
            int col = n0 + n0w + j * 8 + q * 2;
            float2 v0 = { acc[mi][j][0], acc[mi][j][1] };
            float2 v1 = { acc[mi][j][2], acc[mi][j][3] };
            *(float2*)&C[(size_t)row * G4 + col]       = v0;
            *(float2*)&C[(size_t)(row + 8) * G4 + col] = v1;
        }
    }
}

// ---------------- 4) persistent recurrent kernel: fp16 1-term, W resident ----------------
// 128 CTAs: dir = cta>>6, jt = cta&63 -> gate cols [jt*64, +64) = 16 hidden.
// gates[32b][64j] = h[32,1024] @ W^T, fp16 in, fp32 accum.
// W fp16 resident in SMEM (144KB); h streamed per step in 2 k-chunks of 512.
// SMEM: W 147456 | A 2 x 33280 | gates 8192 = 222208 bytes.
#define RS_WH   0
#define RS_A    147456
#define RS_ABUF 33280      // 32 rows x 520 halves x 2B
#define RS_GT   (RS_A + 2 * RS_ABUF)     // 214016
#define RS_SMEM (RS_GT + 8192)           // 222208

__global__ __launch_bounds__(256, 1) void lstm_f16(int layer, float* __restrict__ dout)
{
    extern __shared__ char sm8[];
    uint32_t sb = smem_u32(sm8);
    float* gates_s = (float*)(sm8 + RS_GT);

    int tid  = threadIdx.x;
    int wid  = tid >> 5;
    int lane = tid & 31;
    int cta  = blockIdx.x;
    int d    = cta >> 6;
    int jt   = cta & 63;
    int j0g  = jt * 64;
    int hbase = jt * 16;

    const __half* WhG = g_Whh16[layer][d];
    const float* xgb = g_xg[d];
    __half* hb = g_h16 + (size_t)d * 2 * BATCH * HID;   // [pp][b][k]

    // ---- prologue: resident W (16 chunks x 64 rows x 64 k, row stride 72 halves) ----
#pragma unroll 4
    for (int c = 0; c < 32; c++) {
        int idx = tid + c * 256;
        int ck = idx >> 9, rem = idx & 511;
        int r = rem >> 3, q = rem & 7;
        cp16(sb + RS_WH + (uint32_t)(((ck * 64 + r) * 72 + q * 8) * 2),
             WhG + (size_t)(j0g + r) * KDIM + ck * 64 + q * 8);
    }
    cp_commit(); cp_wait0(); __syncthreads();

    uint32_t w_lane = (uint32_t)(((wid * 8 + (lane & 7)) * 72 + ((lane >> 3) & 1) * 8) * 2);
    uint32_t a_lane = (uint32_t)(((lane & 15) * 520 + (lane >> 4) * 8) * 2);

    int b = tid & 31;
    int hrow = tid >> 5;          // 0..7
    float c_reg[2] = {0.0f, 0.0f};

    int s_row = tid >> 6, s_q = tid & 63;  // staging: idx = tid + i*256 -> row idx>>6, q idx&63

    for (int t = 0; t < SEQ; t++) {
        int time = d ? (SEQ - 1 - t) : t;
        int rp = t & 1, wp = rp ^ 1;
        const __half* hin = hb + (size_t)rp * BATCH * HID;

        // xg prefetch for the pointwise tail
        float4 xv[2];
#pragma unroll
        for (int it = 0; it < 2; it++) {
            int hl16 = hrow + it * 8;
            xv[it] = *(const float4*)(xgb + (size_t)time * BATCH * G4
                                      + (size_t)b * G4 + j0g + hl16 * 4);
        }

        float acc[2][4];
#pragma unroll
        for (int mi = 0; mi < 2; mi++)
#pragma unroll
            for (int e = 0; e < 4; e++) acc[mi][e] = 0.0f;

        // stage one k=512 chunk of h (32 rows x 512 halves, row stride 520)
        auto stage = [&](int bf, int k0) {
            uint32_t base = sb + RS_A + bf * RS_ABUF;
#pragma unroll
            for (int i = 0; i < 8; i++) {
                int row = s_row + i * 4;
                uint32_t off = (uint32_t)((row * 520 + s_q * 8) * 2);
                cp16(base + off, hin + (size_t)row * HID + k0 + s_q * 8);
            }
            cp_commit();
        };

        stage(0, 0);
        int bf = 0;
#pragma unroll 1
        for (int ch = 0; ch < 2; ch++) {
            if (ch == 0) { stage(1, 512); cp_wait1(); }
            else         { cp_wait0(); }
            __syncthreads();
            uint32_t ab = sb + RS_A + bf * RS_ABUF + a_lane;
#pragma unroll
            for (int ks = 0; ks < 32; ks++) {
                int kk = ch * 32 + ks;
                uint32_t wa = sb + RS_WH + (kk >> 2) * 9216 + (kk & 3) * 32 + w_lane;
                uint32_t a0[4], a1[4], b0, b1;
                ldsm_x4(a0[0], a0[1], a0[2], a0[3], ab + ks * 32);
                ldsm_x4(a1[0], a1[1], a1[2], a1[3], ab + 16640 + ks * 32);
                ldsm_x2(b0, b1, wa);
                mma_f16(acc[0][0], acc[0][1], acc[0][2], acc[0][3],
                        a0[0], a0[1], a0[2], a0[3], b0, b1);
                mma_f16(acc[1][0], acc[1][1], acc[1][2], acc[1][3],
                        a1[0], a1[1], a1[2], a1[3], b0, b1);
            }
            __syncthreads();
            bf ^= 1;
        }

        // ---- accumulators -> gates_s[b][j] ----
        {
            int g = lane >> 2, q2 = (lane & 3) * 2;
#pragma unroll
            for (int mi = 0; mi < 2; mi++) {
                float2 v0 = { acc[mi][0], acc[mi][1] };
                float2 v1 = { acc[mi][2], acc[mi][3] };
                *(float2*)&gates_s[(mi * 16 + g) * 64 + wid * 8 + q2]     = v0;
                *(float2*)&gates_s[(mi * 16 + g + 8) * 64 + wid * 8 + q2] = v1;
            }
        }
        __syncthreads();

        // ---- pointwise: thread owns (b, hl16) for it=0,1 ----
#pragma unroll
        for (int it = 0; it < 2; it++) {
            int hl16 = hrow + it * 8;
            float4 gq = *(const float4*)&gates_s[b * 64 + hl16 * 4];
            float gi = gq.x + xv[it].x;
            float gf = gq.y + xv[it].y;
            float gg = gq.z + xv[it].z;
            float go = gq.w + xv[it].w;

            float iv = 1.0f / (1.0f + expf(-gi));
            float fv = 1.0f / (1.0f + expf(-gf));
            float gv = tanhf(gg);
            float ov = 1.0f / (1.0f + expf(-go));

            float c = fv * c_reg[it] + iv * gv;
            float hn = ov * tanhf(c);
            c_reg[it] = c;

            int hg = hbase + hl16;
            __half hh, hl;
            split_f16(hn, hh, hl);
            hb[(size_t)wp * BATCH * HID + (size_t)b * HID + hg] = hh;

            if (layer == 0) {
                size_t arow = ((size_t)time * BATCH + b) * KDIM + hg;
                g_Axh[d][arow] = hh;
                g_Axl[d][arow] = hl;
            } else {
                dout[(size_t)time * BATCH * 2 * HID + (size_t)b * 2 * HID + d * HID + hg] = hn;
            }
            if (time == SEQ - 1) {
                dout[OUT_HALL + (size_t)layer * BATCH * 2 * HID + (size_t)b * 2 * HID + d * HID + hg] = hn;
                dout[OUT_CALL + (size_t)layer * BATCH * 2 * HID + (size_t)b * 2 * HID + d * HID + hg] = c;
            }
        }

        // ---- grid barrier ----
        if (t < SEQ - 1) {
            __syncthreads();
            if (tid == 0) {
                unsigned arr = atom_add_rel(&g_bar_count, 1u);
                if (arr == (unsigned)((t + 1) * NCTA - 1)) {
                    st_rel(&g_bar_gen, (unsigned)(t + 1));
                } else {
                    while (ld_acq(&g_bar_gen) < (unsigned)(t + 1)) { }
                }
            }
            __syncthreads();
        }
    }
}

// ---------------- host launcher ----------------
extern "C" void kernel_launch(void* const* d_in, const int* in_sizes, int n_in,
                              void* d_out, int out_size)
{
    const float* x    = (const float*)d_in[0];
    const float* wihf = (const float*)d_in[1];
    const float* whhf = (const float*)d_in[2];
    const float* wihb = (const float*)d_in[3];
    const float* whhb = (const float*)d_in[4];
    float* out = (float*)d_out;
    (void)in_sizes; (void)n_in; (void)out_size;

    cudaFuncSetAttribute(gemm_mma, cudaFuncAttributeMaxDynamicSharedMemorySize, GM_SMEM);
    cudaFuncSetAttribute(lstm_f16, cudaFuncAttributeMaxDynamicSharedMemorySize, RS_SMEM);

    repack_w<<<dim3(G4, 8), 256>>>(wihf, whhf, wihb, whhb);
    conv_x_f16<<<MROWS * KDIM / 1024, 256>>>(x);

    for (int layer = 0; layer < 2; layer++) {
        zero_state<<<128, 512>>>();
        gemm_mma<<<dim3(G4 / 64, MROWS / 128, 2), 256, GM_SMEM>>>(layer);
        lstm_f16<<<NCTA, 256, RS_SMEM>>>(layer, out);
    }
}

// round 9
// speedup vs baseline: 5.2306x; 1.1442x over previous
#include <cuda_runtime.h>
#include <cuda_fp16.h>
#include <math.h>
#include <stdint.h>

// ---------------- problem constants ----------------
#define SEQ   256
#define BATCH 32
#define HID   1024
#define G4    4096
#define KDIM  1024
#define MROWS (SEQ*BATCH)

#define NCTA  128           // persistent grid (2 dirs x 64 j-tiles of 64 gate cols)

// output layout inside d_out (floats)
#define OUT_HALL   (SEQ*BATCH*2*HID)
#define OUT_CALL   (OUT_HALL + 2*BATCH*2*HID)

// ---------------- device scratch ----------------
__device__ float  g_xg  [2][SEQ*BATCH*G4];       // per-direction xg
__device__ __half g_Wih16[2][2][G4*KDIM];        // gate-permuted W_ih fp16 (input GEMM)
__device__ __half g_Whh16[2][2][G4*KDIM];        // gate-permuted W_hh fp16 (recurrence)
__device__ __half g_Axh[2][MROWS*KDIM];          // GEMM A hi ([0]=x layer0, [dir] layer1)
__device__ __half g_Axl[2][MROWS*KDIM];          // GEMM A lo
__device__ __half g_h16[2*2*BATCH*HID];          // [dir][pp][b][k] recurrent h fp16
__device__ unsigned g_bar_count;
__device__ unsigned g_bar_gen;

// ---------------- sync / async-copy helpers ----------------
__device__ __forceinline__ unsigned ld_acq(const unsigned* p) {
    unsigned v; asm volatile("ld.acquire.gpu.u32 %0, [%1];" : "=r"(v) : "l"(p) : "memory"); return v;
}
__device__ __forceinline__ void st_rel(unsigned* p, unsigned v) {
    asm volatile("st.release.gpu.u32 [%0], %1;" :: "l"(p), "r"(v) : "memory");
}
__device__ __forceinline__ unsigned atom_add_rel(unsigned* p, unsigned v) {
    unsigned o; asm volatile("atom.release.gpu.add.u32 %0, [%1], %2;"
                             : "=r"(o) : "l"(p), "r"(v) : "memory"); return o;
}
__device__ __forceinline__ void cp16(uint32_t s, const void* g) {
    asm volatile("cp.async.cg.shared.global [%0], [%1], 16;" :: "r"(s), "l"(g));
}
__device__ __forceinline__ void cp_commit() { asm volatile("cp.async.commit_group;"); }
__device__ __forceinline__ void cp_wait1()  { asm volatile("cp.async.wait_group 1;" ::: "memory"); }
__device__ __forceinline__ void cp_wait0()  { asm volatile("cp.async.wait_group 0;" ::: "memory"); }

__device__ __forceinline__ uint32_t smem_u32(const void* p) {
    return (uint32_t)__cvta_generic_to_shared(p);
}

// ---------------- mma.sync / ldmatrix helpers (base PTX, sm_80+) ----------------
__device__ __forceinline__ void ldsm_x4(uint32_t& r0, uint32_t& r1, uint32_t& r2, uint32_t& r3,
                                        uint32_t addr) {
    asm volatile("ldmatrix.sync.aligned.m8n8.x4.shared.b16 {%0,%1,%2,%3}, [%4];"
                 : "=r"(r0), "=r"(r1), "=r"(r2), "=r"(r3) : "r"(addr));
}
__device__ __forceinline__ void ldsm_x2(uint32_t& r0, uint32_t& r1, uint32_t addr) {
    asm volatile("ldmatrix.sync.aligned.m8n8.x2.shared.b16 {%0,%1}, [%2];"
                 : "=r"(r0), "=r"(r1) : "r"(addr));
}
__device__ __forceinline__ void mma_f16(float& c0, float& c1, float& c2, float& c3,
                                        uint32_t a0, uint32_t a1, uint32_t a2, uint32_t a3,
                                        uint32_t b0, uint32_t b1) {
    asm volatile("mma.sync.aligned.m16n8k16.row.col.f32.f16.f16.f32 "
                 "{%0,%1,%2,%3}, {%4,%5,%6,%7}, {%8,%9}, {%0,%1,%2,%3};"
                 : "+f"(c0), "+f"(c1), "+f"(c2), "+f"(c3)
                 : "r"(a0), "r"(a1), "r"(a2), "r"(a3), "r"(b0), "r"(b1));
}

// ---------------- split helper ----------------
__device__ __forceinline__ void split_f16(float x, __half& h, __half& l) {
    h = __float2half_rn(x);
    l = __float2half_rn(x - __half2float(h));
}

// ---------------- 1a) weight gate-permute to fp16: row g*H+h -> 4h+g ----------------
__global__ __launch_bounds__(256) void repack_w(
    const float* __restrict__ wihf, const float* __restrict__ whhf,
    const float* __restrict__ wihb, const float* __restrict__ whhb)
{
    int p = blockIdx.x;
    int m = blockIdx.y;
    int dir   = m >> 2;
    int typ   = (m >> 1) & 1;          // 0 = ih, 1 = hh
    int layer = m & 1;
    int srow  = (p & 3) * HID + (p >> 2);

    const float* base = dir ? (typ ? whhb : wihb) : (typ ? whhf : wihf);
    const float* src  = base + (size_t)layer * G4 * KDIM;
    __half* dst = (typ ? g_Whh16[layer][dir] : g_Wih16[layer][dir]) + (size_t)p * KDIM;

    int c = threadIdx.x * 4;
    float4 v = *(const float4*)&src[(size_t)srow * KDIM + c];
    __half2 a = {__float2half_rn(v.x), __float2half_rn(v.y)};
    __half2 b = {__float2half_rn(v.z), __float2half_rn(v.w)};
    *(__half2*)&dst[c]     = a;
    *(__half2*)&dst[c + 2] = b;
}

// ---------------- 1b) fp32 x -> fp16 hi/lo for layer-0 GEMM A ----------------
__global__ __launch_bounds__(256) void conv_x_f16(const float* __restrict__ x)
{
    size_t i = ((size_t)blockIdx.x * 256 + threadIdx.x) * 4;
    float4 v = *(const float4*)&x[i];
    __half h0, l0, h1, l1, h2, l2, h3, l3;
    split_f16(v.x, h0, l0); split_f16(v.y, h1, l1);
    split_f16(v.z, h2, l2); split_f16(v.w, h3, l3);
    __half2 hh0 = {h0, h1}, hh1 = {h2, h3};
    __half2 ll0 = {l0, l1}, ll1 = {l2, l3};
    *(__half2*)&g_Axh[0][i]     = hh0; *(__half2*)&g_Axh[0][i + 2] = hh1;
    *(__half2*)&g_Axl[0][i]     = ll0; *(__half2*)&g_Axl[0][i + 2] = ll1;
}

// ---------------- 2) zero recurrent h + barrier vars ----------------
__global__ __launch_bounds__(512) void zero_state() {
    int i = blockIdx.x * blockDim.x + threadIdx.x;
    if (i == 0) { g_bar_count = 0u; g_bar_gen = 0u; }
    ((uint32_t*)g_h16)[i] = 0u;
}

// ---------------- 3) input GEMM: fp16 2-term (A split hi/lo, W single) ----------------
#define GM_SA  40
#define GM_AH  0
#define GM_AL  5120
#define GM_WH  10240
#define GM_STG 12800
#define GM_SMEM (2 * GM_STG * 2)

__global__ __launch_bounds__(256, 2) void gemm_mma(int layer)
{
    extern __shared__ __half gsm[];

    int tid = threadIdx.x;
    int wid = tid >> 5;
    int lane = tid & 31;
    int dir = blockIdx.z;
    int n0 = blockIdx.x * 64;
    int m0 = blockIdx.y * 128;

    const __half* Ah = g_Axh[layer == 0 ? 0 : dir];
    const __half* Al = g_Axl[layer == 0 ? 0 : dir];
    const __half* W  = g_Wih16[layer][dir];

    uint32_t sb = smem_u32(gsm);

    int arow0 = tid >> 2, aq = tid & 3;
    int wrow  = tid >> 2, wq = tid & 3;
    auto stage = [&](int buf, int k0) {
        uint32_t base = sb + buf * GM_STG * 2;
#pragma unroll
        for (int i = 0; i < 2; i++) {
            int row = arow0 + i * 64;
            uint32_t d = base + (row * GM_SA + aq * 8) * 2;
            size_t s = (size_t)(m0 + row) * KDIM + k0 + aq * 8;
            cp16(d + GM_AH * 2, Ah + s);
            cp16(d + GM_AL * 2, Al + s);
        }
        {
            uint32_t d = base + (wrow * GM_SA + wq * 8) * 2;
            size_t s = (size_t)(n0 + wrow) * KDIM + k0 + wq * 8;
            cp16(d + GM_WH * 2, W + s);
        }
        cp_commit();
    };

    int m0w = (wid >> 1) * 32;
    int n0w = (wid & 1) * 32;
    int a_row = m0w + (lane & 15);
    int a_col = (lane >> 4) * 8;
    int w_n   = n0w + ((lane >> 4) & 1) * 8 + (lane & 7);
    int w_col = ((lane >> 3) & 1) * 8;

    float acc[2][4][4];
#pragma unroll
    for (int mi = 0; mi < 2; mi++)
#pragma unroll
        for (int j = 0; j < 4; j++)
#pragma unroll
            for (int e = 0; e < 4; e++) acc[mi][j][e] = 0.0f;

    stage(0, 0);
    int buf = 0;
#pragma unroll 1
    for (int ch = 0; ch < KDIM / 32; ch++) {
        if (ch < KDIM / 32 - 1) { stage(buf ^ 1, (ch + 1) * 32); cp_wait1(); }
        else                    { cp_wait0(); }
        __syncthreads();
        uint32_t base = sb + buf * GM_STG * 2;
#pragma unroll
        for (int ks = 0; ks < 2; ks++) {
            uint32_t aH[2][4], aL[2][4], wH[2][4];
#pragma unroll
            for (int mi = 0; mi < 2; mi++) {
                uint32_t ao = base + ((a_row + mi * 16) * GM_SA + ks * 16 + a_col) * 2;
                ldsm_x4(aH[mi][0], aH[mi][1], aH[mi][2], aH[mi][3], ao + GM_AH * 2);
                ldsm_x4(aL[mi][0], aL[mi][1], aL[mi][2], aL[mi][3], ao + GM_AL * 2);
            }
#pragma unroll
            for (int jp = 0; jp < 2; jp++) {
                uint32_t wo = base + ((w_n + jp * 16) * GM_SA + ks * 16 + w_col) * 2;
                ldsm_x4(wH[jp][0], wH[jp][1], wH[jp][2], wH[jp][3], wo + GM_WH * 2);
            }
#pragma unroll
            for (int mi = 0; mi < 2; mi++) {
#pragma unroll
                for (int j = 0; j < 4; j++) {
                    int jp = j >> 1, hi = (j & 1) * 2;
                    float* c = acc[mi][j];
                    mma_f16(c[0], c[1], c[2], c[3],
                            aH[mi][0], aH[mi][1], aH[mi][2], aH[mi][3],
                            wH[jp][hi], wH[jp][hi + 1]);
                    mma_f16(c[0], c[1], c[2], c[3],
                            aL[mi][0], aL[mi][1], aL[mi][2], aL[mi][3],
                            wH[jp][hi], wH[jp][hi + 1]);
                }
            }
        }
        __syncthreads();
        buf ^= 1;
    }

    float* C = g_xg[dir];
    int g = lane >> 2, q = lane & 3;
#pragma unroll
    for (int mi = 0; mi < 2; mi++) {
        int row = m0 + m0w + mi * 16 + g;
#pragma unroll
        for (int j = 0; j < 4; j++) {
            int col = n0 + n0w + j * 8 + q * 2;
            float2 v0 = { acc[mi][j][0], acc[mi][j][1] };
            float2 v1 = { acc[mi][j][2], acc[mi][j][3] };
            *(float2*)&C[(size_t)row * G4 + col]       = v0;
            *(float2*)&C[(size_t)(row + 8) * G4 + col] = v1;
        }
    }
}

// ---------------- 4) persistent recurrent kernel: W fragments in registers ----------------
// 128 CTAs x 512 threads (16 warps). dir = cta>>6, jt = cta&63 -> gate cols [jt*64,+64).
// Warp w: k-slice ksl = w>>1 (k in [ksl*128,+128)), n-column nc = w&1 (j in [nc*32,+32)).
// W fragments (64 regs/thread) loaded once per layer. Per step: stage h (64KB), one MMA
// pass with no intra-loop syncs, 8-slice fp32 reduction fused into pointwise.
// SMEM: A 32 x 1032 halves = 66048 (region 66560, also W-staging scratch 64x520) |
//       partials 8 slices x 32b x 68f = 69632.  Total 136192 bytes.
#define RS_A     0
#define RS_ASTR  1032            // A row stride in halves
#define RS_P     66560
#define RS_PSTR  68              // partials row stride in floats
#define RS_PSLC  (32 * RS_PSTR)  // floats per slice (2176)
#define RS_SMEM  (RS_P + 8 * RS_PSLC * 4)   // 136192

__global__ __launch_bounds__(512, 1) void lstm_f16(int layer, float* __restrict__ dout)
{
    extern __shared__ char sm8[];
    uint32_t sb = smem_u32(sm8);
    float* part = (float*)(sm8 + RS_P);

    int tid  = threadIdx.x;
    int wid  = tid >> 5;
    int lane = tid & 31;
    int cta  = blockIdx.x;
    int d    = cta >> 6;
    int jt   = cta & 63;
    int j0g  = jt * 64;
    int hbase = jt * 16;
    int ksl = wid >> 1;          // k slice 0..7
    int nc  = wid & 1;           // n column 0..1

    const __half* WhG = g_Whh16[layer][d];
    const float* xgb = g_xg[d];
    __half* hb = g_h16 + (size_t)d * 2 * BATCH * HID;   // [pp][b][k]

    // ---- prologue: W fragments into registers (2 smem staging passes) ----
    // Each pass stages W rows [j0g, +64), k [p*512, +512) as [64 rows][520-half stride].
    // 64 rows x 64 16B-chunks = 4096 cp16 -> 8 iterations of 512 threads.
    uint32_t wf[8][4][2];
#pragma unroll 1
    for (int p = 0; p < 2; p++) {
#pragma unroll
        for (int i = 0; i < 8; i++) {
            int idx = tid + i * 512;
            int r = idx >> 6, g = idx & 63;        // r: 0..63, g: 0..63
            cp16(sb + RS_A + (uint32_t)(r * 1040 + g * 16),
                 WhG + (size_t)(j0g + r) * KDIM + p * 512 + g * 8);
        }
        cp_commit(); cp_wait0(); __syncthreads();
        if ((ksl >> 2) == p) {
            int lk = (ksl & 3) * 128;     // local k base within this pass
#pragma unroll
            for (int ks = 0; ks < 8; ks++)
#pragma unroll
                for (int nt = 0; nt < 4; nt++) {
                    uint32_t addr = sb + RS_A
                        + (uint32_t)((nc * 32 + nt * 8 + (lane & 7)) * 1040
                                     + (lk + ks * 16 + ((lane >> 3) & 1) * 8) * 2);
                    ldsm_x2(wf[ks][nt][0], wf[ks][nt][1], addr);
                }
        }
        __syncthreads();
    }

    uint32_t a_lane = (uint32_t)((lane & 15) * (RS_ASTR * 2) + (lane >> 4) * 16);
    int b  = tid & 31;
    int hl = tid >> 5;            // 0..15 (one hidden index per thread)
    float c_reg = 0.0f;

    for (int t = 0; t < SEQ; t++) {
        int time = d ? (SEQ - 1 - t) : t;
        int rp = t & 1, wp = rp ^ 1;
        const __half* hin = hb + (size_t)rp * BATCH * HID;

        // xg prefetch (consumed in pointwise)
        float4 xv = *(const float4*)(xgb + (size_t)time * BATCH * G4
                                     + (size_t)b * G4 + j0g + hl * 4);

        // ---- stage full h tile: 32 rows x 1024 halves ----
#pragma unroll
        for (int i = 0; i < 8; i++) {
            int idx = tid + i * 512;
            int r = idx >> 7, g = idx & 127;
            cp16(sb + RS_A + (uint32_t)(r * (RS_ASTR * 2) + g * 16),
                 hin + (size_t)r * HID + g * 8);
        }
        cp_commit(); cp_wait0(); __syncthreads();

        // ---- MMA pass: no syncs, W in regs ----
        float acc[2][4][4];
#pragma unroll
        for (int mi = 0; mi < 2; mi++)
#pragma unroll
            for (int nt = 0; nt < 4; nt++)
#pragma unroll
                for (int e = 0; e < 4; e++) acc[mi][nt][e] = 0.0f;

        uint32_t ab = sb + RS_A + a_lane + (uint32_t)(ksl * 256);  // ksl*128 halves
#pragma unroll
        for (int ks = 0; ks < 8; ks++) {
            uint32_t a0[4], a1[4];
            ldsm_x4(a0[0], a0[1], a0[2], a0[3], ab + ks * 32);
            ldsm_x4(a1[0], a1[1], a1[2], a1[3], ab + 16 * (RS_ASTR * 2) + ks * 32);
#pragma unroll
            for (int nt = 0; nt < 4; nt++) {
                mma_f16(acc[0][nt][0], acc[0][nt][1], acc[0][nt][2], acc[0][nt][3],
                        a0[0], a0[1], a0[2], a0[3], wf[ks][nt][0], wf[ks][nt][1]);
                mma_f16(acc[1][nt][0], acc[1][nt][1], acc[1][nt][2], acc[1][nt][3],
                        a1[0], a1[1], a1[2], a1[3], wf[ks][nt][0], wf[ks][nt][1]);
            }
        }

        // ---- partials -> smem slice ksl ----
        {
            int g = lane >> 2, q = lane & 3;
            float* pbase = part + ksl * RS_PSLC;
#pragma unroll
            for (int mi = 0; mi < 2; mi++)
#pragma unroll
                for (int nt = 0; nt < 4; nt++) {
                    int jj = nc * 32 + nt * 8 + q * 2;
                    float2 v0 = { acc[mi][nt][0], acc[mi][nt][1] };
                    float2 v1 = { acc[mi][nt][2], acc[mi][nt][3] };
                    *(float2*)&pbase[(mi * 16 + g) * RS_PSTR + jj]     = v0;
                    *(float2*)&pbase[(mi * 16 + g + 8) * RS_PSTR + jj] = v1;
                }
        }
        __syncthreads();

        // ---- pointwise: thread owns (b, hl); reduce 8 slices ----
        float gi = xv.x, gf = xv.y, gg = xv.z, go = xv.w;
#pragma unroll
        for (int s = 0; s < 8; s++) {
            float4 v = *(const float4*)&part[s * RS_PSLC + b * RS_PSTR + hl * 4];
            gi += v.x; gf += v.y; gg += v.z; go += v.w;
        }

        float iv = 1.0f / (1.0f + expf(-gi));
        float fv = 1.0f / (1.0f + expf(-gf));
        float gv = tanhf(gg);
        float ov = 1.0f / (1.0f + expf(-go));

        float c = fv * c_reg + iv * gv;
        float hn = ov * tanhf(c);
        c_reg = c;

        int hg = hbase + hl;
        __half hh, hlw;
        split_f16(hn, hh, hlw);
        hb[(size_t)wp * BATCH * HID + (size_t)b * HID + hg] = hh;

        if (layer == 0) {
            size_t arow = ((size_t)time * BATCH + b) * KDIM + hg;
            g_Axh[d][arow] = hh;
            g_Axl[d][arow] = hlw;
        } else {
            dout[(size_t)time * BATCH * 2 * HID + (size_t)b * 2 * HID + d * HID + hg] = hn;
        }
        if (time == SEQ - 1) {
            dout[OUT_HALL + (size_t)layer * BATCH * 2 * HID + (size_t)b * 2 * HID + d * HID + hg] = hn;
            dout[OUT_CALL + (size_t)layer * BATCH * 2 * HID + (size_t)b * 2 * HID + d * HID + hg] = c;
        }

        // ---- grid barrier ----
        if (t < SEQ - 1) {
            __syncthreads();
            if (tid == 0) {
                unsigned arr = atom_add_rel(&g_bar_count, 1u);
                if (arr == (unsigned)((t + 1) * NCTA - 1)) {
                    st_rel(&g_bar_gen, (unsigned)(t + 1));
                } else {
                    while (ld_acq(&g_bar_gen) < (unsigned)(t + 1)) { }
                }
            }
            __syncthreads();
        }
    }
}

// ---------------- host launcher ----------------
extern "C" void kernel_launch(void* const* d_in, const int* in_sizes, int n_in,
                              void* d_out, int out_size)
{
    const float* x    = (const float*)d_in[0];
    const float* wihf = (const float*)d_in[1];
    const float* whhf = (const float*)d_in[2];
    const float* wihb = (const float*)d_in[3];
    const float* whhb = (const float*)d_in[4];
    float* out = (float*)d_out;
    (void)in_sizes; (void)n_in; (void)out_size;

    cudaFuncSetAttribute(gemm_mma, cudaFuncAttributeMaxDynamicSharedMemorySize, GM_SMEM);
    cudaFuncSetAttribute(lstm_f16, cudaFuncAttributeMaxDynamicSharedMemorySize, RS_SMEM);

    repack_w<<<dim3(G4, 8), 256>>>(wihf, whhf, wihb, whhb);
    conv_x_f16<<<MROWS * KDIM / 1024, 256>>>(x);

    for (int layer = 0; layer < 2; layer++) {
        zero_state<<<128, 512>>>();
        gemm_mma<<<dim3(G4 / 64, MROWS / 128, 2), 256, GM_SMEM>>>(layer);
        lstm_f16<<<NCTA, 512, RS_SMEM>>>(layer, out);
    }
}